// round 11
// baseline (speedup 1.0000x reference)
#include <cuda_runtime.h>

#define NSEQ 512
#define DDIM 128
#define RTOT (NSEQ*NSEQ)   /* 262144 positions */

// Scratch (allocation-free rule: __device__ globals, zero-initialized).
__device__ float g_lt[RTOT*DDIM];  // left  compact: [h][kc*CP + jc] (tf32)
__device__ float g_rt[RTOT*DDIM];  // right compact: [h][kc*CP + ic] (tf32)
__device__ float g_og[RTOT*DDIM];  // out-gate compact: [q][h] (fallback only)
__device__ float g_mm[RTOT*DDIM];  // einsum out compact: [d][ic*CP + jc]
__device__ float g_w[6*DDIM*DDIM]; // tf32 weights: Wl,Wlg,Wr,Wrg,Wog,Wo

__device__ int g_act[512];
__device__ int g_cnt, g_cnt2, g_CP, g_CP2, g_fb, g_nzg;

__device__ __forceinline__ float sigmoidf_(float v) {
    return 1.0f / (1.0f + expf(-v));
}
__device__ __forceinline__ unsigned f2tf(float f) {
    unsigned u; asm("cvt.rna.tf32.f32 %0, %1;" : "=r"(u) : "f"(f)); return u;
}
__device__ __forceinline__ float tf32r(float f) { return __uint_as_float(f2tf(f)); }

__device__ __forceinline__ void mma8(float* c, const unsigned* a, const unsigned* b) {
    asm volatile("mma.sync.aligned.m16n8k8.row.col.f32.tf32.tf32.f32 "
        "{%0,%1,%2,%3},{%4,%5,%6,%7},{%8,%9},{%0,%1,%2,%3};"
        : "+f"(c[0]), "+f"(c[1]), "+f"(c[2]), "+f"(c[3])
        : "r"(a[0]), "r"(a[1]), "r"(a[2]), "r"(a[3]), "r"(b[0]), "r"(b[1]));
}
__device__ __forceinline__ unsigned smem_u32(const void* p) {
    return (unsigned)__cvta_generic_to_shared(p);
}
__device__ __forceinline__ void cpa16(unsigned dst, const void* src) {
    asm volatile("cp.async.cg.shared.global [%0], [%1], 16;" :: "r"(dst), "l"(src));
}
#define CP_COMMIT asm volatile("cp.async.commit_group;")
#define CP_WAIT0  asm volatile("cp.async.wait_group 0;")
#define CP_WAIT2  asm volatile("cp.async.wait_group 2;")

// ---------------------------------------------------------------------------
// Kernel 0: compact active list; fallback if olnb != 0. Also resets gate flag.
// ---------------------------------------------------------------------------
__global__ void compact_kernel(const int* __restrict__ sm,
                               const float* __restrict__ olnb)
{
    __shared__ int sc[512];
    __shared__ int nz;
    const int t = threadIdx.x;
    if (t == 0) { nz = 0; g_nzg = 0; }
    __syncthreads();
    if (t < 128 && olnb[t] != 0.0f) atomicOr(&nz, 1);
    const int mv = (sm[t] != 0) ? 1 : 0;
    sc[t] = mv;
    __syncthreads();
    for (int o = 1; o < 512; o <<= 1) {
        int v = (t >= o) ? sc[t - o] : 0;
        __syncthreads();
        sc[t] += v;
        __syncthreads();
    }
    int cnt = sc[511];
    const int fb = nz;
    if (fb) { g_act[t] = t; cnt = 512; }
    else {
        if (mv) g_act[sc[t] - 1] = t;
        if (t >= cnt) g_act[t] = 0;
    }
    if (t == 0) {
        g_cnt = cnt; g_cnt2 = cnt * cnt;
        const int CP = ((cnt + 127) >> 7) << 7;
        g_CP = CP; g_CP2 = CP * CP; g_fb = fb;
    }
}

// ---------------------------------------------------------------------------
// Kernel 0b: tf32-round the 6 weight matrices into g_w once.
// Also detects nonzero GATE weights (planes 1,3,4) -> g_nzg.
// ---------------------------------------------------------------------------
__global__ __launch_bounds__(256) void prep_w_kernel(
    const float* __restrict__ w0, const float* __restrict__ w1,
    const float* __restrict__ w2, const float* __restrict__ w3,
    const float* __restrict__ w4, const float* __restrict__ w5)
{
    const float* srcs[6] = { w0, w1, w2, w3, w4, w5 };
    const int idx = blockIdx.x * 256 + threadIdx.x;   // 384*256 = 98304 exact
    const int plane = idx >> 14;
    const float sv = srcs[plane][idx & 16383];
    g_w[idx] = tf32r(sv);
    const int isgate = (plane == 1) | (plane == 3) | (plane == 4);
    const int bad = isgate && (sv != 0.0f);
    if (__any_sync(0xffffffffu, bad) && (threadIdx.x & 31) == 0)
        atomicOr(&g_nzg, 1);
}

// ---------------------------------------------------------------------------
// Kernel 1: fused LN + projections, tf32 mma. Block = 128 pairs, 512 thr.
// FAST PATH (gates all zero): single dual pass (Wl, Wr); merged lt/rt
// epilogue (rt buffer aliases As, which is dead after the GEMM).
// FALLBACK: original 3-pass (Wl+Wlg, Wr+Wrg, Wog).
// ---------------------------------------------------------------------------
#define PROJ_DYN_FLOATS (128*132 + 4*16*136 + 128*132)
__global__ __launch_bounds__(512) void proj_kernel(
    const float* __restrict__ x,
    const float* __restrict__ lng, const float* __restrict__ lnb,
    const int*   __restrict__ sm,
    const float* __restrict__ bl,  const float* __restrict__ blg,
    const float* __restrict__ br,  const float* __restrict__ brg,
    const float* __restrict__ bog)
{
    const int cnt2 = g_cnt2;
    const int p0 = blockIdx.x * 128;
    if (p0 >= cnt2) return;
    const int cnt = g_cnt, CP = g_CP;
    const size_t CP2 = (size_t)g_CP2;
    const int gz = (g_nzg == 0);

    extern __shared__ float dyn[];
    float (*As)[132]     = (float(*)[132])dyn;                         // 128x132
    float (*Bs)[16][136] = (float(*)[16][136])(dyn + 128*132);         // [2][16][136]
    float (*Gs)[16][136] = (float(*)[16][136])(dyn + 128*132 + 2*16*136);
    float (*Ep)[132]     = (float(*)[132])(dyn + 128*132 + 4*16*136);  // 128h x 132m

    __shared__ int   s_q[128];
    __shared__ int   s_r[128];
    __shared__ float s_mk[128];

    const int tid = threadIdx.x;
    if (tid < 128) {
        const int p = p0 + tid;
        if (p < cnt2) {
            const int kc = p / cnt, jc = p - kc * cnt;
            const int i = g_act[kc], j = g_act[jc];
            s_r[tid]  = (i << 9) + j;
            s_mk[tid] = (float)(sm[i] * sm[j]);
            s_q[tid]  = kc * CP + jc;
        } else { s_r[tid] = 0; s_mk[tid] = 0.0f; s_q[tid] = -1; }
    }

    const unsigned bsAddr = smem_u32(&Bs[0][0][0]);
    const unsigned gsAddr = smem_u32(&Gs[0][0][0]);
    const int lkk = tid >> 5, lc4 = (tid & 31) * 4;
    const unsigned ld0 = (unsigned)((lkk*136 + lc4) << 2);

    // Prefetch pass-0 chunk 0 (overlaps LN below).
    cpa16(bsAddr + ld0, g_w + 0*16384 + lkk*128 + lc4);
    cpa16(gsAddr + ld0, g_w + (gz ? 2 : 1)*16384 + lkk*128 + lc4);
    CP_COMMIT;
    __syncthreads();

    // Fused LayerNorm of the 128 gathered rows -> As (tf32). 4 thr/row.
    {
        const int row = tid >> 2, l4 = tid & 3;
        const float* xr = x + (size_t)s_r[row] * DDIM;
        float s = 0.0f, sq = 0.0f;
        #pragma unroll
        for (int j = 0; j < 8; ++j) {
            const float4 v = *(const float4*)&xr[l4 * 4 + j * 16];
            s  += v.x + v.y + v.z + v.w;
            sq += v.x*v.x + v.y*v.y + v.z*v.z + v.w*v.w;
        }
        s  += __shfl_xor_sync(0xffffffffu, s,  1);
        sq += __shfl_xor_sync(0xffffffffu, sq, 1);
        s  += __shfl_xor_sync(0xffffffffu, s,  2);
        sq += __shfl_xor_sync(0xffffffffu, sq, 2);
        const float mu  = s * (1.0f / DDIM);
        const float var = sq * (1.0f / DDIM) - mu * mu;
        const float rs  = rsqrtf(var + 1e-5f);
        #pragma unroll
        for (int j = 0; j < 8; ++j) {
            const int c = l4 * 4 + j * 16;
            const float4 v  = *(const float4*)&xr[c];
            const float4 gv = *(const float4*)&lng[c];
            const float4 bv = *(const float4*)&lnb[c];
            float4 o;
            o.x = tf32r((v.x - mu) * rs * gv.x + bv.x);
            o.y = tf32r((v.y - mu) * rs * gv.y + bv.y);
            o.z = tf32r((v.z - mu) * rs * gv.z + bv.z);
            o.w = tf32r((v.w - mu) * rs * gv.w + bv.w);
            *(float4*)&As[row][c] = o;
        }
    }
    __syncthreads();

    const int wid = tid >> 5, lane = tid & 31;
    const int g = lane >> 2, tig = lane & 3;
    const int wm = wid & 3, wn = wid >> 2;   // 4 x 4 warps
    const int m0 = wm * 32, n0 = wn * 32;

    if (gz) {
        // ================= FAST PATH: one dual pass: acc1=Wl, acc2=Wr ======
        float acc1[2][4][4] = {};
        float acc2[2][4][4] = {};
        const float* W1 = g_w + 0*16384;
        const float* W2 = g_w + 2*16384;

        int buf = 0;
        #pragma unroll 1
        for (int ch = 0; ch < 8; ++ch) {
            CP_WAIT0;
            __syncthreads();
            if (ch < 7) {
                const int kc = (ch + 1) * 16;
                const unsigned off = (unsigned)((((buf^1)*16*136) + lkk*136 + lc4) << 2);
                cpa16(bsAddr + off, W1 + (kc + lkk) * 128 + lc4);
                cpa16(gsAddr + off, W2 + (kc + lkk) * 128 + lc4);
                CP_COMMIT;
            }
            const int kc = ch * 16;
            #pragma unroll
            for (int ks = 0; ks < 16; ks += 8) {
                unsigned af[2][4], bf[4][2], gf[4][2];
                #pragma unroll
                for (int mt = 0; mt < 2; ++mt) {
                    const int m = m0 + mt * 16 + g;
                    af[mt][0] = __float_as_uint(As[m    ][kc + ks + tig]);
                    af[mt][1] = __float_as_uint(As[m + 8][kc + ks + tig]);
                    af[mt][2] = __float_as_uint(As[m    ][kc + ks + tig + 4]);
                    af[mt][3] = __float_as_uint(As[m + 8][kc + ks + tig + 4]);
                }
                #pragma unroll
                for (int nt = 0; nt < 4; ++nt) {
                    const int n = n0 + nt * 8 + g;
                    bf[nt][0] = __float_as_uint(Bs[buf][ks + tig    ][n]);
                    bf[nt][1] = __float_as_uint(Bs[buf][ks + tig + 4][n]);
                    gf[nt][0] = __float_as_uint(Gs[buf][ks + tig    ][n]);
                    gf[nt][1] = __float_as_uint(Gs[buf][ks + tig + 4][n]);
                }
                #pragma unroll
                for (int mt = 0; mt < 2; ++mt)
                    #pragma unroll
                    for (int nt = 0; nt < 4; ++nt) {
                        mma8(acc1[mt][nt], af[mt], bf[nt]);
                        mma8(acc2[mt][nt], af[mt], gf[nt]);
                    }
            }
            buf ^= 1;
        }

        // Merged epilogue: lt -> Ep, rt -> EpR (aliases As, dead after GEMM).
        float (*EpR)[132] = As;
        __syncthreads();   // all As reads (last chunk mma) complete
        #pragma unroll
        for (int mt = 0; mt < 2; ++mt)
            #pragma unroll
            for (int nt = 0; nt < 4; ++nt)
                #pragma unroll
                for (int e = 0; e < 4; ++e) {
                    const int m = m0 + mt * 16 + g + ((e >> 1) << 3);
                    const int h = n0 + nt * 8 + 2 * tig + (e & 1);
                    float vl = (acc1[mt][nt][e] + bl[h]) * s_mk[m];
                    vl *= sigmoidf_(blg[h]);
                    Ep[h][m] = tf32r(vl);
                    float vr = (acc2[mt][nt][e] + br[h]) * s_mk[m];
                    vr *= sigmoidf_(brg[h]);
                    EpR[h][m] = tf32r(vr);
                }
        __syncthreads();
        #pragma unroll
        for (int it = 0; it < 32; ++it) {
            const int idx = it * 512 + tid;
            const int h = idx >> 7, m = idx & 127;
            const int q = s_q[m];
            if (q >= 0) {
                g_lt[(size_t)h * CP2 + q] = Ep[h][m];
                g_rt[(size_t)h * CP2 + q] = EpR[h][m];
            }
        }
        return;
    }

    // ================= FALLBACK: original 3-pass path ======================
    const float* b1s[3] = { bl, br, bog };
    const float* b2s[3] = { blg, brg, bog };

    #pragma unroll 1
    for (int pass = 0; pass < 3; ++pass) {
        const float* W1 = g_w + (size_t)(pass * 2) * 16384;   // 0,2,4
        const float* W2 = g_w + (size_t)(pass * 2 + 1) * 16384;
        const int dual = (pass < 2);

        float acc1[2][4][4] = {};
        float acc2[2][4][4] = {};

        int buf = 0;
        #pragma unroll 1
        for (int ch = 0; ch < 8; ++ch) {
            CP_WAIT0;
            __syncthreads();
            if (ch < 7) {
                const int kc = (ch + 1) * 16;
                const unsigned off = (unsigned)((((buf^1)*16*136) + lkk*136 + lc4) << 2);
                cpa16(bsAddr + off, W1 + (kc + lkk) * 128 + lc4);
                if (dual)
                    cpa16(gsAddr + off, W2 + (kc + lkk) * 128 + lc4);
                CP_COMMIT;
            }
            const int kc = ch * 16;
            #pragma unroll
            for (int ks = 0; ks < 16; ks += 8) {
                unsigned af[2][4], bf[4][2], gf[4][2];
                #pragma unroll
                for (int mt = 0; mt < 2; ++mt) {
                    const int m = m0 + mt * 16 + g;
                    af[mt][0] = __float_as_uint(As[m    ][kc + ks + tig]);
                    af[mt][1] = __float_as_uint(As[m + 8][kc + ks + tig]);
                    af[mt][2] = __float_as_uint(As[m    ][kc + ks + tig + 4]);
                    af[mt][3] = __float_as_uint(As[m + 8][kc + ks + tig + 4]);
                }
                #pragma unroll
                for (int nt = 0; nt < 4; ++nt) {
                    const int n = n0 + nt * 8 + g;
                    bf[nt][0] = __float_as_uint(Bs[buf][ks + tig    ][n]);
                    bf[nt][1] = __float_as_uint(Bs[buf][ks + tig + 4][n]);
                    if (dual) {
                        gf[nt][0] = __float_as_uint(Gs[buf][ks + tig    ][n]);
                        gf[nt][1] = __float_as_uint(Gs[buf][ks + tig + 4][n]);
                    }
                }
                #pragma unroll
                for (int mt = 0; mt < 2; ++mt)
                    #pragma unroll
                    for (int nt = 0; nt < 4; ++nt) {
                        mma8(acc1[mt][nt], af[mt], bf[nt]);
                        if (dual) mma8(acc2[mt][nt], af[mt], gf[nt]);
                    }
            }
            buf ^= 1;
        }

        // Hoisted prefetch of next pass chunk 0 into buf 0 (overlaps epilogue).
        if (pass == 0) {
            cpa16(bsAddr + ld0, g_w + 2*16384 + lkk*128 + lc4);
            cpa16(gsAddr + ld0, g_w + 3*16384 + lkk*128 + lc4);
            CP_COMMIT;
        } else if (pass == 1) {
            cpa16(bsAddr + ld0, g_w + 4*16384 + lkk*128 + lc4);
            CP_COMMIT;
        }

        const float* b1 = b1s[pass];
        if (dual) {
            const float* b2 = b2s[pass];
            #pragma unroll
            for (int mt = 0; mt < 2; ++mt)
                #pragma unroll
                for (int nt = 0; nt < 4; ++nt)
                    #pragma unroll
                    for (int e = 0; e < 4; ++e) {
                        const int m = m0 + mt * 16 + g + ((e >> 1) << 3);
                        const int h = n0 + nt * 8 + 2 * tig + (e & 1);
                        float v = (acc1[mt][nt][e] + b1[h]) * s_mk[m];
                        v *= sigmoidf_(acc2[mt][nt][e] + b2[h]);
                        Ep[h][m] = tf32r(v);
                    }
            __syncthreads();
            float* outp = (pass == 0) ? g_lt : g_rt;
            #pragma unroll
            for (int it = 0; it < 32; ++it) {
                const int idx = it * 512 + tid;
                const int h = idx >> 7, m = idx & 127;
                const int q = s_q[m];
                if (q >= 0) outp[(size_t)h * CP2 + q] = Ep[h][m];
            }
            __syncthreads();
        } else {
            // out-gate: direct float2 stores, og[q][h]
            #pragma unroll
            for (int mt = 0; mt < 2; ++mt)
                #pragma unroll
                for (int nt = 0; nt < 4; ++nt) {
                    const int h = n0 + nt * 8 + 2 * tig;
                    const float bh0 = b1[h], bh1 = b1[h + 1];
                    {
                        const int m = m0 + mt * 16 + g;
                        const int q = s_q[m];
                        if (q >= 0) {
                            float2 v = { sigmoidf_(acc1[mt][nt][0] + bh0),
                                         sigmoidf_(acc1[mt][nt][1] + bh1) };
                            *(float2*)&g_og[(size_t)q * DDIM + h] = v;
                        }
                    }
                    {
                        const int m = m0 + mt * 16 + g + 8;
                        const int q = s_q[m];
                        if (q >= 0) {
                            float2 v = { sigmoidf_(acc1[mt][nt][2] + bh0),
                                         sigmoidf_(acc1[mt][nt][3] + bh1) };
                            *(float2*)&g_og[(size_t)q * DDIM + h] = v;
                        }
                    }
                }
        }
    }
}

// ---------------------------------------------------------------------------
// Kernel 2: einsum via tf32 mma. Block tile 128(i) x 64(j), 256 threads
// (4x2 warps, 32x32 warp tile, 32 acc regs -> 3 blocks/SM). 4-stage ring.
// Blocks with z >= 128 perform the inactive-row bo-fill of `out`.
// Grid: (8, 4, 144): x=j-tile(64), y=i-tile(128), z<128 einsum d / z>=128 fill.
// ---------------------------------------------------------------------------
#define EIN_A_STRIDE 136
#define EIN_B_STRIDE 72
#define EIN_A_FLOATS (4*16*EIN_A_STRIDE)
#define EIN_DYN_FLOATS (EIN_A_FLOATS + 4*16*EIN_B_STRIDE)
__global__ __launch_bounds__(256) void einsum_kernel(
    const int* __restrict__ sm, const float* __restrict__ bo,
    float* __restrict__ out)
{
    const int tid = threadIdx.x;

    if (blockIdx.z >= 128) {
        // ---- fill branch: inactive rows -> bo (valid because olnb == 0) ----
        if (g_fb) return;
        const int fb_id = (blockIdx.z - 128) * 32 + blockIdx.y * 8 + blockIdx.x;
        const int lane = tid & 31, wrp = tid >> 5;      // 8 warps, 1 row each
        const float4 b4 = *(const float4*)&bo[lane * 4];
        const int r0 = fb_id * 512;
        #pragma unroll 4
        for (int k = 0; k < 64; ++k) {
            const int r = r0 + k * 8 + wrp;
            const int i = r >> 9, j = r & (NSEQ - 1);
            if (sm[i] * sm[j]) continue;
            *(float4*)&out[(size_t)r * DDIM + lane * 4] = b4;
        }
        return;
    }

    const int cnt = g_cnt;
    const int i0 = blockIdx.y * 128;
    const int j0 = blockIdx.x * 64;
    if (i0 >= cnt || j0 >= cnt) return;
    const int CP = g_CP;
    const size_t CP2 = (size_t)g_CP2;
    const int d = blockIdx.z;
    const float* A = g_rt + (size_t)d * CP2;   // [k][i]
    const float* B = g_lt + (size_t)d * CP2;   // [k][j]

    extern __shared__ float edyn[];
    float (*As)[16][EIN_A_STRIDE] = (float(*)[16][EIN_A_STRIDE])edyn;
    float (*Bs)[16][EIN_B_STRIDE] = (float(*)[16][EIN_B_STRIDE])(edyn + EIN_A_FLOATS);

    const int wid = tid >> 5, lane = tid & 31;
    const int g = lane >> 2, tig = lane & 3;
    const int wm = wid & 3, wn = wid >> 2;   // 4 x 2
    const int m0 = wm * 32, n0 = wn * 32;

    const unsigned asAddr = smem_u32(&As[0][0][0]);
    const unsigned bsAddr = smem_u32(&Bs[0][0][0]);

    // A load: 512 float4/chunk, 2 per thread. B load: 256 float4, 1 per thread.
    const int arow0 = tid >> 5, ac4 = (tid & 31) * 4;        // f = tid: row=f>>5
    const int arow1 = (tid + 256) >> 5;                      // second A float4
    const int brow = tid >> 4, bc4 = (tid & 15) * 4;

    float acc[2][4][4] = {};

    const int kend = (cnt + 15) & ~15;
    const int nch = kend >> 4;

    // prologue: prefetch chunks 0..2 into stages 0..2 (empty commits allowed)
    #pragma unroll
    for (int pc = 0; pc < 3; ++pc) {
        if (pc < nch) {
            const unsigned aoff0 = (unsigned)((pc*16*EIN_A_STRIDE + arow0*EIN_A_STRIDE + ac4) << 2);
            const unsigned aoff1 = (unsigned)((pc*16*EIN_A_STRIDE + arow1*EIN_A_STRIDE + ac4) << 2);
            const unsigned boff  = (unsigned)((pc*16*EIN_B_STRIDE + brow*EIN_B_STRIDE + bc4) << 2);
            cpa16(asAddr + aoff0, A + (size_t)(pc*16 + arow0) * CP + i0 + ac4);
            cpa16(asAddr + aoff1, A + (size_t)(pc*16 + arow1) * CP + i0 + ac4);
            cpa16(bsAddr + boff,  B + (size_t)(pc*16 + brow) * CP + j0 + bc4);
        }
        CP_COMMIT;
    }

    #pragma unroll 1
    for (int ch = 0; ch < nch; ++ch) {
        CP_WAIT2;
        __syncthreads();
        const int pf = ch + 3;
        if (pf < nch) {
            const int stg = pf & 3;
            const unsigned aoff0 = (unsigned)((stg*16*EIN_A_STRIDE + arow0*EIN_A_STRIDE + ac4) << 2);
            const unsigned aoff1 = (unsigned)((stg*16*EIN_A_STRIDE + arow1*EIN_A_STRIDE + ac4) << 2);
            const unsigned boff  = (unsigned)((stg*16*EIN_B_STRIDE + brow*EIN_B_STRIDE + bc4) << 2);
            cpa16(asAddr + aoff0, A + (size_t)(pf*16 + arow0) * CP + i0 + ac4);
            cpa16(asAddr + aoff1, A + (size_t)(pf*16 + arow1) * CP + i0 + ac4);
            cpa16(bsAddr + boff,  B + (size_t)(pf*16 + brow) * CP + j0 + bc4);
        }
        CP_COMMIT;
        const int cs = ch & 3;
        #pragma unroll
        for (int ks = 0; ks < 16; ks += 8) {
            unsigned af[2][4], bf[4][2];
            #pragma unroll
            for (int mt = 0; mt < 2; ++mt) {
                const int m = m0 + mt * 16 + g;
                af[mt][0] = __float_as_uint(As[cs][ks + tig    ][m]);
                af[mt][1] = __float_as_uint(As[cs][ks + tig    ][m + 8]);
                af[mt][2] = __float_as_uint(As[cs][ks + tig + 4][m]);
                af[mt][3] = __float_as_uint(As[cs][ks + tig + 4][m + 8]);
            }
            #pragma unroll
            for (int nt = 0; nt < 4; ++nt) {
                const int n = n0 + nt * 8 + g;
                bf[nt][0] = __float_as_uint(Bs[cs][ks + tig    ][n]);
                bf[nt][1] = __float_as_uint(Bs[cs][ks + tig + 4][n]);
            }
            #pragma unroll
            for (int mt = 0; mt < 2; ++mt)
                #pragma unroll
                for (int nt = 0; nt < 4; ++nt)
                    mma8(acc[mt][nt], af[mt], bf[nt]);
        }
    }

    #pragma unroll
    for (int mt = 0; mt < 2; ++mt)
        #pragma unroll
        for (int nt = 0; nt < 4; ++nt) {
            const int row = i0 + m0 + mt * 16 + g;
            const int col = j0 + n0 + nt * 8 + 2 * tig;
            float2 v0 = { acc[mt][nt][0], acc[mt][nt][1] };
            float2 v1 = { acc[mt][nt][2], acc[mt][nt][3] };
            *(float2*)&g_mm[(size_t)d * CP2 + (size_t)row * CP + col] = v0;
            *(float2*)&g_mm[(size_t)d * CP2 + (size_t)(row + 8) * CP + col] = v1;
        }
}

// ---------------------------------------------------------------------------
// Kernel 3: final: out = (_ln_h(mm) * og) @ Wo + bo. 64 pairs/block, 256 thr
// (2 blocks/SM co-residency). FAST PATH: og = sigmoid(bog[d]) inline.
// ---------------------------------------------------------------------------
#define FIN_DYN_FLOATS (128*68 + 64*132 + 2*16*136)
__global__ __launch_bounds__(256) void final_kernel(
    const float* __restrict__ olng, const float* __restrict__ olnb,
    const float* __restrict__ bog,
    const float* __restrict__ bo,   float* __restrict__ out)
{
    const int cnt2 = g_cnt2;
    const int p0 = blockIdx.x * 64;
    if (p0 >= cnt2) return;
    const int cnt = g_cnt, CP = g_CP;
    const size_t CP2 = (size_t)g_CP2;
    const int gz = (g_nzg == 0);

    extern __shared__ float dyn[];
    float (*s_mm)[68]    = (float(*)[68])dyn;                        // 128d x 68p
    float (*s_v)[132]    = (float(*)[132])(dyn + 128*68);            // 64p x 132d
    float (*Bs)[16][136] = (float(*)[16][136])(dyn + 128*68 + 64*132);

    __shared__ int s_q[64], s_ro[64];

    const int tid = threadIdx.x;
    if (tid < 64) {
        const int p = p0 + tid;
        if (p < cnt2) {
            const int ic = p / cnt, jc = p - ic * cnt;
            s_q[tid]  = ic * CP + jc;
            s_ro[tid] = (g_act[ic] << 9) + g_act[jc];
        } else { s_q[tid] = 0; s_ro[tid] = -1; }
    }

    const unsigned bsAddr = smem_u32(&Bs[0][0][0]);
    const float* Wo = g_w + 5 * 16384;
    const int lkk0 = tid >> 5, lc4 = (tid & 31) * 4;

    // prefetch Wo chunk 0 (overlaps gather + LN): 16 rows via 2 rounds
    #pragma unroll
    for (int u2 = 0; u2 < 2; ++u2) {
        const int kk = lkk0 + u2 * 8;
        cpa16(bsAddr + (unsigned)((kk*136 + lc4) << 2), Wo + kk * 128 + lc4);
    }
    CP_COMMIT;
    __syncthreads();

    #pragma unroll
    for (int it = 0; it < 32; ++it) {
        const int idx = it * 256 + tid;
        const int dd = idx >> 6, pp = idx & 63;
        s_mm[dd][pp] = g_mm[(size_t)dd * CP2 + s_q[pp]];
    }
    __syncthreads();

    {   // LN over d + gate: 4 threads per pair, 32 d's each
        const int p = tid >> 2, e = tid & 3;
        float s = 0.0f, sq = 0.0f;
        #pragma unroll
        for (int k = 0; k < 32; ++k) {
            const float v = s_mm[e * 32 + k][p];
            s += v; sq += v * v;
        }
        s  += __shfl_xor_sync(0xffffffffu, s,  1);
        sq += __shfl_xor_sync(0xffffffffu, sq, 1);
        s  += __shfl_xor_sync(0xffffffffu, s,  2);
        sq += __shfl_xor_sync(0xffffffffu, sq, 2);
        const float mu  = s * (1.0f / 128.0f);
        const float var = sq * (1.0f / 128.0f) - mu * mu;
        const float rs  = rsqrtf(var + 1e-5f);
        const float* ogr = g_og + (size_t)s_q[p] * DDIM + e * 32;
        #pragma unroll
        for (int j = 0; j < 8; ++j) {
            const int dbase = e * 32 + j * 4;
            float4 og4;
            if (gz) {
                const float4 bg = *(const float4*)&bog[dbase];
                og4.x = sigmoidf_(bg.x); og4.y = sigmoidf_(bg.y);
                og4.z = sigmoidf_(bg.z); og4.w = sigmoidf_(bg.w);
            } else {
                og4 = *(const float4*)&ogr[j * 4];
            }
            const float4 gg = *(const float4*)&olng[dbase];
            const float4 bb = *(const float4*)&olnb[dbase];
            float4 o;
            o.x = tf32r(((s_mm[dbase+0][p] - mu) * rs * gg.x + bb.x) * og4.x);
            o.y = tf32r(((s_mm[dbase+1][p] - mu) * rs * gg.y + bb.y) * og4.y);
            o.z = tf32r(((s_mm[dbase+2][p] - mu) * rs * gg.z + bb.z) * og4.z);
            o.w = tf32r(((s_mm[dbase+3][p] - mu) * rs * gg.w + bb.w) * og4.w);
            *(float4*)&s_v[p][dbase] = o;
        }
    }

    const int wid = tid >> 5, lane = tid & 31;
    const int g = lane >> 2, tig = lane & 3;
    const int wm = wid & 1, wn = wid >> 1;    // 2 x 4 warps, 32x32 tiles
    const int m0 = wm * 32, n0 = wn * 32;

    float acc[2][4][4] = {};

    int buf = 0;
    #pragma unroll 1
    for (int ch = 0; ch < 8; ++ch) {
        CP_WAIT0;
        __syncthreads();
        if (ch < 7) {
            const int kc = (ch + 1) * 16;
            #pragma unroll
            for (int u2 = 0; u2 < 2; ++u2) {
                const int kk = lkk0 + u2 * 8;
                const unsigned off = (unsigned)((((buf^1)*16*136) + kk*136 + lc4) << 2);
                cpa16(bsAddr + off, Wo + (kc + kk) * 128 + lc4);
            }
            CP_COMMIT;
        }
        const int kc = ch * 16;
        #pragma unroll
        for (int ks = 0; ks < 16; ks += 8) {
            unsigned af[2][4], bf[4][2];
            #pragma unroll
            for (int mt = 0; mt < 2; ++mt) {
                const int m = m0 + mt * 16 + g;
                af[mt][0] = __float_as_uint(s_v[m    ][kc + ks + tig]);
                af[mt][1] = __float_as_uint(s_v[m + 8][kc + ks + tig]);
                af[mt][2] = __float_as_uint(s_v[m    ][kc + ks + tig + 4]);
                af[mt][3] = __float_as_uint(s_v[m + 8][kc + ks + tig + 4]);
            }
            #pragma unroll
            for (int nt = 0; nt < 4; ++nt) {
                const int n = n0 + nt * 8 + g;
                bf[nt][0] = __float_as_uint(Bs[buf][ks + tig    ][n]);
                bf[nt][1] = __float_as_uint(Bs[buf][ks + tig + 4][n]);
            }
            #pragma unroll
            for (int mt = 0; mt < 2; ++mt)
                #pragma unroll
                for (int nt = 0; nt < 4; ++nt)
                    mma8(acc[mt][nt], af[mt], bf[nt]);
        }
        buf ^= 1;
    }

    #pragma unroll
    for (int mt = 0; mt < 2; ++mt)
        #pragma unroll
        for (int nt = 0; nt < 4; ++nt) {
            const int h = n0 + nt * 8 + 2 * tig;
            const float bh0 = bo[h], bh1 = bo[h + 1];
            {
                const int m = m0 + mt * 16 + g;
                const int ro = s_ro[m];
                if (ro >= 0) {
                    float2 v = { acc[mt][nt][0] + bh0, acc[mt][nt][1] + bh1 };
                    *(float2*)&out[(size_t)ro * DDIM + h] = v;
                }
            }
            {
                const int m = m0 + mt * 16 + g + 8;
                const int ro = s_ro[m];
                if (ro >= 0) {
                    float2 v = { acc[mt][nt][2] + bh0, acc[mt][nt][3] + bh1 };
                    *(float2*)&out[(size_t)ro * DDIM + h] = v;
                }
            }
        }
}

// ---------------------------------------------------------------------------
extern "C" void kernel_launch(void* const* d_in, const int* in_sizes, int n_in,
                              void* d_out, int out_size)
{
    const float* x    = (const float*)d_in[0];
    const int*   sm   = (const int*)  d_in[1];
    const float* lng  = (const float*)d_in[2];
    const float* lnb  = (const float*)d_in[3];
    const float* Wl   = (const float*)d_in[4];
    const float* bl   = (const float*)d_in[5];
    const float* Wr   = (const float*)d_in[6];
    const float* br   = (const float*)d_in[7];
    const float* Wlg  = (const float*)d_in[8];
    const float* blg  = (const float*)d_in[9];
    const float* Wrg  = (const float*)d_in[10];
    const float* brg  = (const float*)d_in[11];
    const float* Wog  = (const float*)d_in[12];
    const float* bog  = (const float*)d_in[13];
    const float* olng = (const float*)d_in[14];
    const float* olnb = (const float*)d_in[15];
    const float* Wo   = (const float*)d_in[16];
    const float* bo   = (const float*)d_in[17];
    float* out = (float*)d_out;

    const int projdyn = PROJ_DYN_FLOATS * 4;
    const int eindyn  = EIN_DYN_FLOATS * 4;
    const int findyn  = FIN_DYN_FLOATS * 4;
    cudaFuncSetAttribute(proj_kernel,
                         cudaFuncAttributeMaxDynamicSharedMemorySize, projdyn);
    cudaFuncSetAttribute(einsum_kernel,
                         cudaFuncAttributeMaxDynamicSharedMemorySize, eindyn);
    cudaFuncSetAttribute(final_kernel,
                         cudaFuncAttributeMaxDynamicSharedMemorySize, findyn);

    compact_kernel<<<1, 512>>>(sm, olnb);
    prep_w_kernel<<<384, 256>>>(Wl, Wlg, Wr, Wrg, Wog, Wo);

    proj_kernel<<<2048, 512, projdyn>>>(x, lng, lnb, sm, bl, blg, br, brg, bog);

    // z in [0,128): einsum d-planes (tiles 128x64); z in [128,144): fused
    // bo-fill (512 blocks, id = (z-128)*32 + y*8 + x).
    einsum_kernel<<<dim3(8, 4, 144), 256, eindyn>>>(sm, bo, out);

    final_kernel<<<4096, 256, findyn>>>(olng, olnb, bog, bo, out);
}

// round 12
// speedup vs baseline: 1.0813x; 1.0813x over previous
#include <cuda_runtime.h>

#define NSEQ 512
#define DDIM 128
#define RTOT (NSEQ*NSEQ)   /* 262144 positions */

// Scratch (allocation-free rule: __device__ globals, zero-initialized).
__device__ float g_lt[RTOT*DDIM];  // left  compact: [h][kc*CP + jc] (tf32)
__device__ float g_rt[RTOT*DDIM];  // right compact: [h][kc*CP + ic] (tf32)
__device__ float g_og[RTOT*DDIM];  // out-gate compact: [q][h] (fallback only)
__device__ float g_mm[RTOT*DDIM];  // einsum out compact: [d][ic*CP + jc]
__device__ float g_w[6*DDIM*DDIM]; // tf32 weights: Wl,Wlg,Wr,Wrg,Wog,Wo

__device__ int g_act[512];
__device__ int g_cnt, g_cnt2, g_CP, g_CP2, g_fb, g_nzg;

__device__ __forceinline__ float sigmoidf_(float v) {
    return 1.0f / (1.0f + expf(-v));
}
__device__ __forceinline__ unsigned f2tf(float f) {
    unsigned u; asm("cvt.rna.tf32.f32 %0, %1;" : "=r"(u) : "f"(f)); return u;
}
__device__ __forceinline__ float tf32r(float f) { return __uint_as_float(f2tf(f)); }

__device__ __forceinline__ void mma8(float* c, const unsigned* a, const unsigned* b) {
    asm volatile("mma.sync.aligned.m16n8k8.row.col.f32.tf32.tf32.f32 "
        "{%0,%1,%2,%3},{%4,%5,%6,%7},{%8,%9},{%0,%1,%2,%3};"
        : "+f"(c[0]), "+f"(c[1]), "+f"(c[2]), "+f"(c[3])
        : "r"(a[0]), "r"(a[1]), "r"(a[2]), "r"(a[3]), "r"(b[0]), "r"(b[1]));
}
__device__ __forceinline__ unsigned smem_u32(const void* p) {
    return (unsigned)__cvta_generic_to_shared(p);
}
__device__ __forceinline__ void cpa16(unsigned dst, const void* src) {
    asm volatile("cp.async.cg.shared.global [%0], [%1], 16;" :: "r"(dst), "l"(src));
}
#define CP_COMMIT asm volatile("cp.async.commit_group;")
#define CP_WAIT0  asm volatile("cp.async.wait_group 0;")
#define CP_WAIT2  asm volatile("cp.async.wait_group 2;")

// ---------------------------------------------------------------------------
// Kernel 0: compact active list; fallback if olnb != 0. Also resets gate flag.
// ---------------------------------------------------------------------------
__global__ void compact_kernel(const int* __restrict__ sm,
                               const float* __restrict__ olnb)
{
    __shared__ int sc[512];
    __shared__ int nz;
    const int t = threadIdx.x;
    if (t == 0) { nz = 0; g_nzg = 0; }
    __syncthreads();
    if (t < 128 && olnb[t] != 0.0f) atomicOr(&nz, 1);
    const int mv = (sm[t] != 0) ? 1 : 0;
    sc[t] = mv;
    __syncthreads();
    for (int o = 1; o < 512; o <<= 1) {
        int v = (t >= o) ? sc[t - o] : 0;
        __syncthreads();
        sc[t] += v;
        __syncthreads();
    }
    int cnt = sc[511];
    const int fb = nz;
    if (fb) { g_act[t] = t; cnt = 512; }
    else {
        if (mv) g_act[sc[t] - 1] = t;
        if (t >= cnt) g_act[t] = 0;
    }
    if (t == 0) {
        g_cnt = cnt; g_cnt2 = cnt * cnt;
        const int CP = ((cnt + 127) >> 7) << 7;
        g_CP = CP; g_CP2 = CP * CP; g_fb = fb;
    }
}

// ---------------------------------------------------------------------------
// Kernel 0b: tf32-round the 6 weight matrices into g_w once.
// Also detects nonzero GATE weights (planes 1,3,4) -> g_nzg.
// ---------------------------------------------------------------------------
__global__ __launch_bounds__(256) void prep_w_kernel(
    const float* __restrict__ w0, const float* __restrict__ w1,
    const float* __restrict__ w2, const float* __restrict__ w3,
    const float* __restrict__ w4, const float* __restrict__ w5)
{
    const float* srcs[6] = { w0, w1, w2, w3, w4, w5 };
    const int idx = blockIdx.x * 256 + threadIdx.x;   // 384*256 = 98304 exact
    const int plane = idx >> 14;
    const float sv = srcs[plane][idx & 16383];
    g_w[idx] = tf32r(sv);
    const int isgate = (plane == 1) | (plane == 3) | (plane == 4);
    const int bad = isgate && (sv != 0.0f);
    if (__any_sync(0xffffffffu, bad) && (threadIdx.x & 31) == 0)
        atomicOr(&g_nzg, 1);
}

// ---------------------------------------------------------------------------
// Kernel 1: fused LN + projections, tf32 mma. Block = 64 pairs, 256 thr,
// __launch_bounds__(256,2) -> 2 blocks/SM so LN/epilogue phases of one block
// overlap the GEMM of the other.
// FAST PATH (gates all zero): single dual pass (Wl, Wr); merged lt/rt
// epilogue (rt buffer aliases the As region, dead after the GEMM).
// FALLBACK: 3-pass (Wl+Wlg, Wr+Wrg, Wog), same 256-thread shape.
// ---------------------------------------------------------------------------
#define PROJ_AS_FLOATS 8704                     /* max(64*132, 128*68) */
#define PROJ_DYN_FLOATS (PROJ_AS_FLOATS + 2*16*136 + 2*16*136 + 128*68)
__global__ __launch_bounds__(256, 2) void proj_kernel(
    const float* __restrict__ x,
    const float* __restrict__ lng, const float* __restrict__ lnb,
    const int*   __restrict__ sm,
    const float* __restrict__ bl,  const float* __restrict__ blg,
    const float* __restrict__ br,  const float* __restrict__ brg,
    const float* __restrict__ bog)
{
    const int cnt2 = g_cnt2;
    const int p0 = blockIdx.x * 64;
    if (p0 >= cnt2) return;
    const int cnt = g_cnt, CP = g_CP;
    const size_t CP2 = (size_t)g_CP2;
    const int gz = (g_nzg == 0);

    extern __shared__ float dyn[];
    float (*As)[132]     = (float(*)[132])dyn;                              // 64x132
    float (*Bs)[16][136] = (float(*)[16][136])(dyn + PROJ_AS_FLOATS);       // [2][16][136]
    float (*Gs)[16][136] = (float(*)[16][136])(dyn + PROJ_AS_FLOATS + 2*16*136);
    float (*Ep)[68]      = (float(*)[68])(dyn + PROJ_AS_FLOATS + 4*16*136); // 128h x 68m

    __shared__ int   s_q[64];
    __shared__ int   s_r[64];
    __shared__ float s_mk[64];

    const int tid = threadIdx.x;
    if (tid < 64) {
        const int p = p0 + tid;
        if (p < cnt2) {
            const int kc = p / cnt, jc = p - kc * cnt;
            const int i = g_act[kc], j = g_act[jc];
            s_r[tid]  = (i << 9) + j;
            s_mk[tid] = (float)(sm[i] * sm[j]);
            s_q[tid]  = kc * CP + jc;
        } else { s_r[tid] = 0; s_mk[tid] = 0.0f; s_q[tid] = -1; }
    }

    const unsigned bsAddr = smem_u32(&Bs[0][0][0]);
    const unsigned gsAddr = smem_u32(&Gs[0][0][0]);
    const int lkk0 = tid >> 5, lc4 = (tid & 31) * 4;   // rows lkk0 and lkk0+8

    // Prefetch pass-0 chunk 0 (overlaps LN below).
    #pragma unroll
    for (int u2 = 0; u2 < 2; ++u2) {
        const int kk = lkk0 + u2 * 8;
        const unsigned off = (unsigned)((kk*136 + lc4) << 2);
        cpa16(bsAddr + off, g_w + 0*16384 + kk*128 + lc4);
        cpa16(gsAddr + off, g_w + (gz ? 2 : 1)*16384 + kk*128 + lc4);
    }
    CP_COMMIT;
    __syncthreads();

    // Fused LayerNorm of the 64 gathered rows -> As (tf32). 4 thr/row.
    {
        const int row = tid >> 2, l4 = tid & 3;
        const float* xr = x + (size_t)s_r[row] * DDIM;
        float s = 0.0f, sq = 0.0f;
        #pragma unroll
        for (int j = 0; j < 8; ++j) {
            const float4 v = *(const float4*)&xr[l4 * 4 + j * 16];
            s  += v.x + v.y + v.z + v.w;
            sq += v.x*v.x + v.y*v.y + v.z*v.z + v.w*v.w;
        }
        s  += __shfl_xor_sync(0xffffffffu, s,  1);
        sq += __shfl_xor_sync(0xffffffffu, sq, 1);
        s  += __shfl_xor_sync(0xffffffffu, s,  2);
        sq += __shfl_xor_sync(0xffffffffu, sq, 2);
        const float mu  = s * (1.0f / DDIM);
        const float var = sq * (1.0f / DDIM) - mu * mu;
        const float rs  = rsqrtf(var + 1e-5f);
        #pragma unroll
        for (int j = 0; j < 8; ++j) {
            const int c = l4 * 4 + j * 16;
            const float4 v  = *(const float4*)&xr[c];
            const float4 gv = *(const float4*)&lng[c];
            const float4 bv = *(const float4*)&lnb[c];
            float4 o;
            o.x = tf32r((v.x - mu) * rs * gv.x + bv.x);
            o.y = tf32r((v.y - mu) * rs * gv.y + bv.y);
            o.z = tf32r((v.z - mu) * rs * gv.z + bv.z);
            o.w = tf32r((v.w - mu) * rs * gv.w + bv.w);
            *(float4*)&As[row][c] = o;
        }
    }
    __syncthreads();

    const int wid = tid >> 5, lane = tid & 31;
    const int g = lane >> 2, tig = lane & 3;
    const int wm = wid & 1, wn = wid >> 1;   // 2 x 4 warps
    const int m0 = wm * 32, n0 = wn * 32;

    if (gz) {
        // ================= FAST PATH: one dual pass: acc1=Wl, acc2=Wr ======
        float acc1[2][4][4] = {};
        float acc2[2][4][4] = {};
        const float* W1 = g_w + 0*16384;
        const float* W2 = g_w + 2*16384;

        int buf = 0;
        #pragma unroll 1
        for (int ch = 0; ch < 8; ++ch) {
            CP_WAIT0;
            __syncthreads();
            if (ch < 7) {
                const int kc = (ch + 1) * 16;
                #pragma unroll
                for (int u2 = 0; u2 < 2; ++u2) {
                    const int kk = lkk0 + u2 * 8;
                    const unsigned off = (unsigned)((((buf^1)*16*136) + kk*136 + lc4) << 2);
                    cpa16(bsAddr + off, W1 + (kc + kk) * 128 + lc4);
                    cpa16(gsAddr + off, W2 + (kc + kk) * 128 + lc4);
                }
                CP_COMMIT;
            }
            const int kc = ch * 16;
            #pragma unroll
            for (int ks = 0; ks < 16; ks += 8) {
                unsigned af[2][4], bf[4][2], gf[4][2];
                #pragma unroll
                for (int mt = 0; mt < 2; ++mt) {
                    const int m = m0 + mt * 16 + g;
                    af[mt][0] = __float_as_uint(As[m    ][kc + ks + tig]);
                    af[mt][1] = __float_as_uint(As[m + 8][kc + ks + tig]);
                    af[mt][2] = __float_as_uint(As[m    ][kc + ks + tig + 4]);
                    af[mt][3] = __float_as_uint(As[m + 8][kc + ks + tig + 4]);
                }
                #pragma unroll
                for (int nt = 0; nt < 4; ++nt) {
                    const int n = n0 + nt * 8 + g;
                    bf[nt][0] = __float_as_uint(Bs[buf][ks + tig    ][n]);
                    bf[nt][1] = __float_as_uint(Bs[buf][ks + tig + 4][n]);
                    gf[nt][0] = __float_as_uint(Gs[buf][ks + tig    ][n]);
                    gf[nt][1] = __float_as_uint(Gs[buf][ks + tig + 4][n]);
                }
                #pragma unroll
                for (int mt = 0; mt < 2; ++mt)
                    #pragma unroll
                    for (int nt = 0; nt < 4; ++nt) {
                        mma8(acc1[mt][nt], af[mt], bf[nt]);
                        mma8(acc2[mt][nt], af[mt], gf[nt]);
                    }
            }
            buf ^= 1;
        }

        // Merged epilogue: lt -> Ep, rt -> EpR (aliases As region, dead now).
        float (*EpR)[68] = (float(*)[68])dyn;
        __syncthreads();   // all As reads (last chunk mma) complete
        #pragma unroll
        for (int mt = 0; mt < 2; ++mt)
            #pragma unroll
            for (int nt = 0; nt < 4; ++nt)
                #pragma unroll
                for (int e = 0; e < 4; ++e) {
                    const int m = m0 + mt * 16 + g + ((e >> 1) << 3);
                    const int h = n0 + nt * 8 + 2 * tig + (e & 1);
                    float vl = (acc1[mt][nt][e] + bl[h]) * s_mk[m];
                    vl *= sigmoidf_(blg[h]);
                    Ep[h][m] = tf32r(vl);
                    float vr = (acc2[mt][nt][e] + br[h]) * s_mk[m];
                    vr *= sigmoidf_(brg[h]);
                    EpR[h][m] = tf32r(vr);
                }
        __syncthreads();
        #pragma unroll
        for (int it = 0; it < 32; ++it) {
            const int idx = it * 256 + tid;
            const int h = idx >> 6, m = idx & 63;
            const int q = s_q[m];
            if (q >= 0) {
                g_lt[(size_t)h * CP2 + q] = Ep[h][m];
                g_rt[(size_t)h * CP2 + q] = EpR[h][m];
            }
        }
        return;
    }

    // ================= FALLBACK: 3-pass path (256-thread shape) ============
    const float* b1s[3] = { bl, br, bog };
    const float* b2s[3] = { blg, brg, bog };

    #pragma unroll 1
    for (int pass = 0; pass < 3; ++pass) {
        const float* W1 = g_w + (size_t)(pass * 2) * 16384;   // 0,2,4
        const float* W2 = g_w + (size_t)(pass * 2 + 1) * 16384;
        const int dual = (pass < 2);

        float acc1[2][4][4] = {};
        float acc2[2][4][4] = {};

        int buf = 0;
        #pragma unroll 1
        for (int ch = 0; ch < 8; ++ch) {
            CP_WAIT0;
            __syncthreads();
            if (ch < 7) {
                const int kc = (ch + 1) * 16;
                #pragma unroll
                for (int u2 = 0; u2 < 2; ++u2) {
                    const int kk = lkk0 + u2 * 8;
                    const unsigned off = (unsigned)((((buf^1)*16*136) + kk*136 + lc4) << 2);
                    cpa16(bsAddr + off, W1 + (kc + kk) * 128 + lc4);
                    if (dual)
                        cpa16(gsAddr + off, W2 + (kc + kk) * 128 + lc4);
                }
                CP_COMMIT;
            }
            const int kc = ch * 16;
            #pragma unroll
            for (int ks = 0; ks < 16; ks += 8) {
                unsigned af[2][4], bf[4][2], gf[4][2];
                #pragma unroll
                for (int mt = 0; mt < 2; ++mt) {
                    const int m = m0 + mt * 16 + g;
                    af[mt][0] = __float_as_uint(As[m    ][kc + ks + tig]);
                    af[mt][1] = __float_as_uint(As[m + 8][kc + ks + tig]);
                    af[mt][2] = __float_as_uint(As[m    ][kc + ks + tig + 4]);
                    af[mt][3] = __float_as_uint(As[m + 8][kc + ks + tig + 4]);
                }
                #pragma unroll
                for (int nt = 0; nt < 4; ++nt) {
                    const int n = n0 + nt * 8 + g;
                    bf[nt][0] = __float_as_uint(Bs[buf][ks + tig    ][n]);
                    bf[nt][1] = __float_as_uint(Bs[buf][ks + tig + 4][n]);
                    if (dual) {
                        gf[nt][0] = __float_as_uint(Gs[buf][ks + tig    ][n]);
                        gf[nt][1] = __float_as_uint(Gs[buf][ks + tig + 4][n]);
                    }
                }
                #pragma unroll
                for (int mt = 0; mt < 2; ++mt)
                    #pragma unroll
                    for (int nt = 0; nt < 4; ++nt) {
                        mma8(acc1[mt][nt], af[mt], bf[nt]);
                        if (dual) mma8(acc2[mt][nt], af[mt], gf[nt]);
                    }
            }
            buf ^= 1;
        }

        // Hoisted prefetch of next pass chunk 0 into buf 0 (overlaps epilogue).
        if (pass == 0) {
            #pragma unroll
            for (int u2 = 0; u2 < 2; ++u2) {
                const int kk = lkk0 + u2 * 8;
                const unsigned off = (unsigned)((kk*136 + lc4) << 2);
                cpa16(bsAddr + off, g_w + 2*16384 + kk*128 + lc4);
                cpa16(gsAddr + off, g_w + 3*16384 + kk*128 + lc4);
            }
            CP_COMMIT;
        } else if (pass == 1) {
            #pragma unroll
            for (int u2 = 0; u2 < 2; ++u2) {
                const int kk = lkk0 + u2 * 8;
                const unsigned off = (unsigned)((kk*136 + lc4) << 2);
                cpa16(bsAddr + off, g_w + 4*16384 + kk*128 + lc4);
            }
            CP_COMMIT;
        }

        const float* b1 = b1s[pass];
        if (dual) {
            const float* b2 = b2s[pass];
            #pragma unroll
            for (int mt = 0; mt < 2; ++mt)
                #pragma unroll
                for (int nt = 0; nt < 4; ++nt)
                    #pragma unroll
                    for (int e = 0; e < 4; ++e) {
                        const int m = m0 + mt * 16 + g + ((e >> 1) << 3);
                        const int h = n0 + nt * 8 + 2 * tig + (e & 1);
                        float v = (acc1[mt][nt][e] + b1[h]) * s_mk[m];
                        v *= sigmoidf_(acc2[mt][nt][e] + b2[h]);
                        Ep[h][m] = tf32r(v);
                    }
            __syncthreads();
            float* outp = (pass == 0) ? g_lt : g_rt;
            #pragma unroll
            for (int it = 0; it < 32; ++it) {
                const int idx = it * 256 + tid;
                const int h = idx >> 6, m = idx & 63;
                const int q = s_q[m];
                if (q >= 0) outp[(size_t)h * CP2 + q] = Ep[h][m];
            }
            __syncthreads();
        } else {
            // out-gate: direct float2 stores, og[q][h]
            #pragma unroll
            for (int mt = 0; mt < 2; ++mt)
                #pragma unroll
                for (int nt = 0; nt < 4; ++nt) {
                    const int h = n0 + nt * 8 + 2 * tig;
                    const float bh0 = b1[h], bh1 = b1[h + 1];
                    {
                        const int m = m0 + mt * 16 + g;
                        const int q = s_q[m];
                        if (q >= 0) {
                            float2 v = { sigmoidf_(acc1[mt][nt][0] + bh0),
                                         sigmoidf_(acc1[mt][nt][1] + bh1) };
                            *(float2*)&g_og[(size_t)q * DDIM + h] = v;
                        }
                    }
                    {
                        const int m = m0 + mt * 16 + g + 8;
                        const int q = s_q[m];
                        if (q >= 0) {
                            float2 v = { sigmoidf_(acc1[mt][nt][2] + bh0),
                                         sigmoidf_(acc1[mt][nt][3] + bh1) };
                            *(float2*)&g_og[(size_t)q * DDIM + h] = v;
                        }
                    }
                }
        }
    }
}

// ---------------------------------------------------------------------------
// Kernel 2: einsum via tf32 mma, 4-stage cp.async ring (wait_group 2).
// Block 128x128, 256 threads (2x4 warps, 64x32 warp tile) — R10 config.
// Blocks with z >= 128 perform the inactive-row bo-fill of `out`.
// ---------------------------------------------------------------------------
#define EIN_DYN_FLOATS (2*4*16*136)
__global__ __launch_bounds__(256) void einsum_kernel(
    const int* __restrict__ sm, const float* __restrict__ bo,
    float* __restrict__ out)
{
    const int tid = threadIdx.x;

    if (blockIdx.z >= 128) {
        // ---- fill branch: inactive rows -> bo (valid because olnb == 0) ----
        if (g_fb) return;
        const int fb_id = (blockIdx.z - 128) * 16 + blockIdx.y * 4 + blockIdx.x;
        const int lane = tid & 31, wrp = tid >> 5;      // 8 warps, 1 row each
        const float4 b4 = *(const float4*)&bo[lane * 4];
        const int r0 = fb_id * 512;
        #pragma unroll 4
        for (int k = 0; k < 64; ++k) {
            const int r = r0 + k * 8 + wrp;
            const int i = r >> 9, j = r & (NSEQ - 1);
            if (sm[i] * sm[j]) continue;
            *(float4*)&out[(size_t)r * DDIM + lane * 4] = b4;
        }
        return;
    }

    const int cnt = g_cnt;
    const int i0 = blockIdx.y * 128;
    const int j0 = blockIdx.x * 128;
    if (i0 >= cnt || j0 >= cnt) return;
    const int CP = g_CP;
    const size_t CP2 = (size_t)g_CP2;
    const int d = blockIdx.z;
    const float* A = g_rt + (size_t)d * CP2;   // [k][i]
    const float* B = g_lt + (size_t)d * CP2;   // [k][j]

    extern __shared__ float edyn[];
    float (*As)[16][136] = (float(*)[16][136])edyn;                 // [4][16][136]
    float (*Bs)[16][136] = (float(*)[16][136])(edyn + 4*16*136);    // [4][16][136]

    const int wid = tid >> 5, lane = tid & 31;
    const int g = lane >> 2, tig = lane & 3;
    const int wm = wid & 1, wn = wid >> 1;   // 2 x 4
    const int m0 = wm * 64, n0 = wn * 32;

    const unsigned asAddr = smem_u32(&As[0][0][0]);
    const unsigned bsAddr = smem_u32(&Bs[0][0][0]);
    const int lkk0 = tid >> 5, lc4 = (tid & 31) * 4;

    float acc[4][4][4] = {};

    const int kend = (cnt + 15) & ~15;
    const int nch = kend >> 4;

    // prologue: prefetch chunks 0..2 into stages 0..2 (empty commits allowed)
    #pragma unroll
    for (int pc = 0; pc < 3; ++pc) {
        if (pc < nch) {
            #pragma unroll
            for (int u2 = 0; u2 < 2; ++u2) {
                const int kk = lkk0 + u2 * 8;
                const unsigned off = (unsigned)((pc*16*136 + kk*136 + lc4) << 2);
                cpa16(asAddr + off, A + (size_t)(pc*16 + kk) * CP + i0 + lc4);
                cpa16(bsAddr + off, B + (size_t)(pc*16 + kk) * CP + j0 + lc4);
            }
        }
        CP_COMMIT;
    }

    #pragma unroll 1
    for (int ch = 0; ch < nch; ++ch) {
        CP_WAIT2;
        __syncthreads();
        const int pf = ch + 3;
        if (pf < nch) {
            const int stg = pf & 3;
            #pragma unroll
            for (int u2 = 0; u2 < 2; ++u2) {
                const int kk = lkk0 + u2 * 8;
                const unsigned off = (unsigned)((stg*16*136 + kk*136 + lc4) << 2);
                cpa16(asAddr + off, A + (size_t)(pf*16 + kk) * CP + i0 + lc4);
                cpa16(bsAddr + off, B + (size_t)(pf*16 + kk) * CP + j0 + lc4);
            }
        }
        CP_COMMIT;
        const int cs = ch & 3;
        #pragma unroll
        for (int ks = 0; ks < 16; ks += 8) {
            unsigned af[4][4], bf[4][2];
            #pragma unroll
            for (int mt = 0; mt < 4; ++mt) {
                const int m = m0 + mt * 16 + g;
                af[mt][0] = __float_as_uint(As[cs][ks + tig    ][m]);
                af[mt][1] = __float_as_uint(As[cs][ks + tig    ][m + 8]);
                af[mt][2] = __float_as_uint(As[cs][ks + tig + 4][m]);
                af[mt][3] = __float_as_uint(As[cs][ks + tig + 4][m + 8]);
            }
            #pragma unroll
            for (int nt = 0; nt < 4; ++nt) {
                const int n = n0 + nt * 8 + g;
                bf[nt][0] = __float_as_uint(Bs[cs][ks + tig    ][n]);
                bf[nt][1] = __float_as_uint(Bs[cs][ks + tig + 4][n]);
            }
            #pragma unroll
            for (int mt = 0; mt < 4; ++mt)
                #pragma unroll
                for (int nt = 0; nt < 4; ++nt)
                    mma8(acc[mt][nt], af[mt], bf[nt]);
        }
    }

    #pragma unroll
    for (int mt = 0; mt < 4; ++mt)
        #pragma unroll
        for (int nt = 0; nt < 4; ++nt) {
            const int row = i0 + m0 + mt * 16 + g;
            const int col = j0 + n0 + nt * 8 + 2 * tig;
            float2 v0 = { acc[mt][nt][0], acc[mt][nt][1] };
            float2 v1 = { acc[mt][nt][2], acc[mt][nt][3] };
            *(float2*)&g_mm[(size_t)d * CP2 + (size_t)row * CP + col] = v0;
            *(float2*)&g_mm[(size_t)d * CP2 + (size_t)(row + 8) * CP + col] = v1;
        }
}

// ---------------------------------------------------------------------------
// Kernel 3: final: out = (_ln_h(mm) * og) @ Wo + bo. 64 pairs/block, 256 thr
// (2 blocks/SM co-residency). FAST PATH: og = sigmoid(bog[d]) inline.
// ---------------------------------------------------------------------------
#define FIN_DYN_FLOATS (128*68 + 64*132 + 2*16*136)
__global__ __launch_bounds__(256) void final_kernel(
    const float* __restrict__ olng, const float* __restrict__ olnb,
    const float* __restrict__ bog,
    const float* __restrict__ bo,   float* __restrict__ out)
{
    const int cnt2 = g_cnt2;
    const int p0 = blockIdx.x * 64;
    if (p0 >= cnt2) return;
    const int cnt = g_cnt, CP = g_CP;
    const size_t CP2 = (size_t)g_CP2;
    const int gz = (g_nzg == 0);

    extern __shared__ float dyn[];
    float (*s_mm)[68]    = (float(*)[68])dyn;                        // 128d x 68p
    float (*s_v)[132]    = (float(*)[132])(dyn + 128*68);            // 64p x 132d
    float (*Bs)[16][136] = (float(*)[16][136])(dyn + 128*68 + 64*132);

    __shared__ int s_q[64], s_ro[64];

    const int tid = threadIdx.x;
    if (tid < 64) {
        const int p = p0 + tid;
        if (p < cnt2) {
            const int ic = p / cnt, jc = p - ic * cnt;
            s_q[tid]  = ic * CP + jc;
            s_ro[tid] = (g_act[ic] << 9) + g_act[jc];
        } else { s_q[tid] = 0; s_ro[tid] = -1; }
    }

    const unsigned bsAddr = smem_u32(&Bs[0][0][0]);
    const float* Wo = g_w + 5 * 16384;
    const int lkk0 = tid >> 5, lc4 = (tid & 31) * 4;

    // prefetch Wo chunk 0 (overlaps gather + LN): 16 rows via 2 rounds
    #pragma unroll
    for (int u2 = 0; u2 < 2; ++u2) {
        const int kk = lkk0 + u2 * 8;
        cpa16(bsAddr + (unsigned)((kk*136 + lc4) << 2), Wo + kk * 128 + lc4);
    }
    CP_COMMIT;
    __syncthreads();

    #pragma unroll
    for (int it = 0; it < 32; ++it) {
        const int idx = it * 256 + tid;
        const int dd = idx >> 6, pp = idx & 63;
        s_mm[dd][pp] = g_mm[(size_t)dd * CP2 + s_q[pp]];
    }
    __syncthreads();

    {   // LN over d + gate: 4 threads per pair, 32 d's each
        const int p = tid >> 2, e = tid & 3;
        float s = 0.0f, sq = 0.0f;
        #pragma unroll
        for (int k = 0; k < 32; ++k) {
            const float v = s_mm[e * 32 + k][p];
            s += v; sq += v * v;
        }
        s  += __shfl_xor_sync(0xffffffffu, s,  1);
        sq += __shfl_xor_sync(0xffffffffu, sq, 1);
        s  += __shfl_xor_sync(0xffffffffu, s,  2);
        sq += __shfl_xor_sync(0xffffffffu, sq, 2);
        const float mu  = s * (1.0f / 128.0f);
        const float var = sq * (1.0f / 128.0f) - mu * mu;
        const float rs  = rsqrtf(var + 1e-5f);
        const float* ogr = g_og + (size_t)s_q[p] * DDIM + e * 32;
        #pragma unroll
        for (int j = 0; j < 8; ++j) {
            const int dbase = e * 32 + j * 4;
            float4 og4;
            if (gz) {
                const float4 bg = *(const float4*)&bog[dbase];
                og4.x = sigmoidf_(bg.x); og4.y = sigmoidf_(bg.y);
                og4.z = sigmoidf_(bg.z); og4.w = sigmoidf_(bg.w);
            } else {
                og4 = *(const float4*)&ogr[j * 4];
            }
            const float4 gg = *(const float4*)&olng[dbase];
            const float4 bb = *(const float4*)&olnb[dbase];
            float4 o;
            o.x = tf32r(((s_mm[dbase+0][p] - mu) * rs * gg.x + bb.x) * og4.x);
            o.y = tf32r(((s_mm[dbase+1][p] - mu) * rs * gg.y + bb.y) * og4.y);
            o.z = tf32r(((s_mm[dbase+2][p] - mu) * rs * gg.z + bb.z) * og4.z);
            o.w = tf32r(((s_mm[dbase+3][p] - mu) * rs * gg.w + bb.w) * og4.w);
            *(float4*)&s_v[p][dbase] = o;
        }
    }

    const int wid = tid >> 5, lane = tid & 31;
    const int g = lane >> 2, tig = lane & 3;
    const int wm = wid & 1, wn = wid >> 1;    // 2 x 4 warps, 32x32 tiles
    const int m0 = wm * 32, n0 = wn * 32;

    float acc[2][4][4] = {};

    int buf = 0;
    #pragma unroll 1
    for (int ch = 0; ch < 8; ++ch) {
        CP_WAIT0;
        __syncthreads();
        if (ch < 7) {
            const int kc = (ch + 1) * 16;
            #pragma unroll
            for (int u2 = 0; u2 < 2; ++u2) {
                const int kk = lkk0 + u2 * 8;
                const unsigned off = (unsigned)((((buf^1)*16*136) + kk*136 + lc4) << 2);
                cpa16(bsAddr + off, Wo + (kc + kk) * 128 + lc4);
            }
            CP_COMMIT;
        }
        const int kc = ch * 16;
        #pragma unroll
        for (int ks = 0; ks < 16; ks += 8) {
            unsigned af[2][4], bf[4][2];
            #pragma unroll
            for (int mt = 0; mt < 2; ++mt) {
                const int m = m0 + mt * 16 + g;
                af[mt][0] = __float_as_uint(s_v[m    ][kc + ks + tig]);
                af[mt][1] = __float_as_uint(s_v[m + 8][kc + ks + tig]);
                af[mt][2] = __float_as_uint(s_v[m    ][kc + ks + tig + 4]);
                af[mt][3] = __float_as_uint(s_v[m + 8][kc + ks + tig + 4]);
            }
            #pragma unroll
            for (int nt = 0; nt < 4; ++nt) {
                const int n = n0 + nt * 8 + g;
                bf[nt][0] = __float_as_uint(Bs[buf][ks + tig    ][n]);
                bf[nt][1] = __float_as_uint(Bs[buf][ks + tig + 4][n]);
            }
            #pragma unroll
            for (int mt = 0; mt < 2; ++mt)
                #pragma unroll
                for (int nt = 0; nt < 4; ++nt)
                    mma8(acc[mt][nt], af[mt], bf[nt]);
        }
        buf ^= 1;
    }

    #pragma unroll
    for (int mt = 0; mt < 2; ++mt)
        #pragma unroll
        for (int nt = 0; nt < 4; ++nt) {
            const int h = n0 + nt * 8 + 2 * tig;
            const float bh0 = bo[h], bh1 = bo[h + 1];
            {
                const int m = m0 + mt * 16 + g;
                const int ro = s_ro[m];
                if (ro >= 0) {
                    float2 v = { acc[mt][nt][0] + bh0, acc[mt][nt][1] + bh1 };
                    *(float2*)&out[(size_t)ro * DDIM + h] = v;
                }
            }
            {
                const int m = m0 + mt * 16 + g + 8;
                const int ro = s_ro[m];
                if (ro >= 0) {
                    float2 v = { acc[mt][nt][2] + bh0, acc[mt][nt][3] + bh1 };
                    *(float2*)&out[(size_t)ro * DDIM + h] = v;
                }
            }
        }
}

// ---------------------------------------------------------------------------
extern "C" void kernel_launch(void* const* d_in, const int* in_sizes, int n_in,
                              void* d_out, int out_size)
{
    const float* x    = (const float*)d_in[0];
    const int*   sm   = (const int*)  d_in[1];
    const float* lng  = (const float*)d_in[2];
    const float* lnb  = (const float*)d_in[3];
    const float* Wl   = (const float*)d_in[4];
    const float* bl   = (const float*)d_in[5];
    const float* Wr   = (const float*)d_in[6];
    const float* br   = (const float*)d_in[7];
    const float* Wlg  = (const float*)d_in[8];
    const float* blg  = (const float*)d_in[9];
    const float* Wrg  = (const float*)d_in[10];
    const float* brg  = (const float*)d_in[11];
    const float* Wog  = (const float*)d_in[12];
    const float* bog  = (const float*)d_in[13];
    const float* olng = (const float*)d_in[14];
    const float* olnb = (const float*)d_in[15];
    const float* Wo   = (const float*)d_in[16];
    const float* bo   = (const float*)d_in[17];
    float* out = (float*)d_out;

    const int projdyn = PROJ_DYN_FLOATS * 4;
    const int eindyn  = EIN_DYN_FLOATS * 4;
    const int findyn  = FIN_DYN_FLOATS * 4;
    cudaFuncSetAttribute(proj_kernel,
                         cudaFuncAttributeMaxDynamicSharedMemorySize, projdyn);
    cudaFuncSetAttribute(einsum_kernel,
                         cudaFuncAttributeMaxDynamicSharedMemorySize, eindyn);
    cudaFuncSetAttribute(final_kernel,
                         cudaFuncAttributeMaxDynamicSharedMemorySize, findyn);

    compact_kernel<<<1, 512>>>(sm, olnb);
    prep_w_kernel<<<384, 256>>>(Wl, Wlg, Wr, Wrg, Wog, Wo);

    proj_kernel<<<4096, 256, projdyn>>>(x, lng, lnb, sm, bl, blg, br, brg, bog);

    // z in [0,128): einsum d-planes; z in [128,160): fused bo-fill.
    einsum_kernel<<<dim3(4, 4, 160), 256, eindyn>>>(sm, bo, out);

    final_kernel<<<4096, 256, findyn>>>(olng, olnb, bog, bo, out);
}

// round 13
// speedup vs baseline: 1.0941x; 1.0119x over previous
#include <cuda_runtime.h>

#define NSEQ 512
#define DDIM 128
#define RTOT (NSEQ*NSEQ)   /* 262144 positions */

// Scratch (allocation-free rule: __device__ globals, zero-initialized).
__device__ float g_lt[RTOT*DDIM];  // left  compact: [h][kc*CP + jc] (tf32)
__device__ float g_rt[RTOT*DDIM];  // right compact: [h][kc*CP + ic] (tf32)
__device__ float g_og[RTOT*DDIM];  // out-gate compact: [q][h] (fallback only)
__device__ float g_mm[RTOT*DDIM];  // einsum out compact: [d][ic*CP + jc]
__device__ float g_w[6*DDIM*DDIM]; // tf32 weights: Wl,Wlg,Wr,Wrg,Wog,Wo

__device__ int g_act[512];
__device__ int g_cnt, g_cnt2, g_CP, g_CP2, g_fb, g_nzg;

__device__ __forceinline__ float sigmoidf_(float v) {
    return 1.0f / (1.0f + expf(-v));
}
__device__ __forceinline__ unsigned f2tf(float f) {
    unsigned u; asm("cvt.rna.tf32.f32 %0, %1;" : "=r"(u) : "f"(f)); return u;
}
__device__ __forceinline__ float tf32r(float f) { return __uint_as_float(f2tf(f)); }

__device__ __forceinline__ void mma8(float* c, const unsigned* a, const unsigned* b) {
    asm volatile("mma.sync.aligned.m16n8k8.row.col.f32.tf32.tf32.f32 "
        "{%0,%1,%2,%3},{%4,%5,%6,%7},{%8,%9},{%0,%1,%2,%3};"
        : "+f"(c[0]), "+f"(c[1]), "+f"(c[2]), "+f"(c[3])
        : "r"(a[0]), "r"(a[1]), "r"(a[2]), "r"(a[3]), "r"(b[0]), "r"(b[1]));
}
__device__ __forceinline__ unsigned smem_u32(const void* p) {
    return (unsigned)__cvta_generic_to_shared(p);
}
__device__ __forceinline__ void cpa16(unsigned dst, const void* src) {
    asm volatile("cp.async.cg.shared.global [%0], [%1], 16;" :: "r"(dst), "l"(src));
}
#define CP_COMMIT asm volatile("cp.async.commit_group;")
#define CP_WAIT0  asm volatile("cp.async.wait_group 0;")
#define CP_WAIT2  asm volatile("cp.async.wait_group 2;")

// PDL: trigger dependent-grid launch / wait for primary completion+visibility.
__device__ __forceinline__ void pdl_trigger() {
    asm volatile("griddepcontrol.launch_dependents;");
}
__device__ __forceinline__ void pdl_wait() {
    asm volatile("griddepcontrol.wait;");
}

// ---------------------------------------------------------------------------
// Kernel 0: compact active list; fallback if olnb != 0. Also resets gate flag.
// ---------------------------------------------------------------------------
__global__ void compact_kernel(const int* __restrict__ sm,
                               const float* __restrict__ olnb)
{
    __shared__ int sc[512];
    __shared__ int nz;
    const int t = threadIdx.x;
    if (t == 0) { nz = 0; g_nzg = 0; }
    __syncthreads();
    if (t < 128 && olnb[t] != 0.0f) atomicOr(&nz, 1);
    const int mv = (sm[t] != 0) ? 1 : 0;
    sc[t] = mv;
    __syncthreads();
    for (int o = 1; o < 512; o <<= 1) {
        int v = (t >= o) ? sc[t - o] : 0;
        __syncthreads();
        sc[t] += v;
        __syncthreads();
    }
    int cnt = sc[511];
    const int fb = nz;
    if (fb) { g_act[t] = t; cnt = 512; }
    else {
        if (mv) g_act[sc[t] - 1] = t;
        if (t >= cnt) g_act[t] = 0;
    }
    if (t == 0) {
        g_cnt = cnt; g_cnt2 = cnt * cnt;
        const int CP = ((cnt + 127) >> 7) << 7;
        g_CP = CP; g_CP2 = CP * CP; g_fb = fb;
    }
}

// ---------------------------------------------------------------------------
// Kernel 0b: tf32-round the 6 weight matrices into g_w once.
// Also detects nonzero GATE weights (planes 1,3,4) -> g_nzg.
// ---------------------------------------------------------------------------
__global__ __launch_bounds__(256) void prep_w_kernel(
    const float* __restrict__ w0, const float* __restrict__ w1,
    const float* __restrict__ w2, const float* __restrict__ w3,
    const float* __restrict__ w4, const float* __restrict__ w5)
{
    const float* srcs[6] = { w0, w1, w2, w3, w4, w5 };
    const int idx = blockIdx.x * 256 + threadIdx.x;   // 384*256 = 98304 exact
    const int plane = idx >> 14;
    const float sv = srcs[plane][idx & 16383];
    g_w[idx] = tf32r(sv);
    const int isgate = (plane == 1) | (plane == 3) | (plane == 4);
    const int bad = isgate && (sv != 0.0f);
    if (__any_sync(0xffffffffu, bad) && (threadIdx.x & 31) == 0)
        atomicOr(&g_nzg, 1);
}

// ---------------------------------------------------------------------------
// Kernel 1: fused LN + projections, tf32 mma. Block = 64 pairs, 256 thr,
// __launch_bounds__(256,2) -> 2 blocks/SM. Triggers dependent (einsum)
// launch right after its GEMM mainloop.
// FAST PATH (gates all zero): single dual pass (Wl, Wr); merged lt/rt
// epilogue. FALLBACK: 3-pass (Wl+Wlg, Wr+Wrg, Wog).
// ---------------------------------------------------------------------------
#define PROJ_AS_FLOATS 8704                     /* max(64*132, 128*68) */
#define PROJ_DYN_FLOATS (PROJ_AS_FLOATS + 2*16*136 + 2*16*136 + 128*68)
__global__ __launch_bounds__(256, 2) void proj_kernel(
    const float* __restrict__ x,
    const float* __restrict__ lng, const float* __restrict__ lnb,
    const int*   __restrict__ sm,
    const float* __restrict__ bl,  const float* __restrict__ blg,
    const float* __restrict__ br,  const float* __restrict__ brg,
    const float* __restrict__ bog)
{
    const int cnt2 = g_cnt2;
    const int p0 = blockIdx.x * 64;
    if (p0 >= cnt2) return;
    const int cnt = g_cnt, CP = g_CP;
    const size_t CP2 = (size_t)g_CP2;
    const int gz = (g_nzg == 0);

    extern __shared__ float dyn[];
    float (*As)[132]     = (float(*)[132])dyn;                              // 64x132
    float (*Bs)[16][136] = (float(*)[16][136])(dyn + PROJ_AS_FLOATS);       // [2][16][136]
    float (*Gs)[16][136] = (float(*)[16][136])(dyn + PROJ_AS_FLOATS + 2*16*136);
    float (*Ep)[68]      = (float(*)[68])(dyn + PROJ_AS_FLOATS + 4*16*136); // 128h x 68m

    __shared__ int   s_q[64];
    __shared__ int   s_r[64];
    __shared__ float s_mk[64];

    const int tid = threadIdx.x;
    if (tid < 64) {
        const int p = p0 + tid;
        if (p < cnt2) {
            const int kc = p / cnt, jc = p - kc * cnt;
            const int i = g_act[kc], j = g_act[jc];
            s_r[tid]  = (i << 9) + j;
            s_mk[tid] = (float)(sm[i] * sm[j]);
            s_q[tid]  = kc * CP + jc;
        } else { s_r[tid] = 0; s_mk[tid] = 0.0f; s_q[tid] = -1; }
    }

    const unsigned bsAddr = smem_u32(&Bs[0][0][0]);
    const unsigned gsAddr = smem_u32(&Gs[0][0][0]);
    const int lkk0 = tid >> 5, lc4 = (tid & 31) * 4;   // rows lkk0 and lkk0+8

    // Prefetch pass-0 chunk 0 (overlaps LN below).
    #pragma unroll
    for (int u2 = 0; u2 < 2; ++u2) {
        const int kk = lkk0 + u2 * 8;
        const unsigned off = (unsigned)((kk*136 + lc4) << 2);
        cpa16(bsAddr + off, g_w + 0*16384 + kk*128 + lc4);
        cpa16(gsAddr + off, g_w + (gz ? 2 : 1)*16384 + kk*128 + lc4);
    }
    CP_COMMIT;
    __syncthreads();

    // Fused LayerNorm of the 64 gathered rows -> As (tf32). 4 thr/row.
    {
        const int row = tid >> 2, l4 = tid & 3;
        const float* xr = x + (size_t)s_r[row] * DDIM;
        float s = 0.0f, sq = 0.0f;
        #pragma unroll
        for (int j = 0; j < 8; ++j) {
            const float4 v = *(const float4*)&xr[l4 * 4 + j * 16];
            s  += v.x + v.y + v.z + v.w;
            sq += v.x*v.x + v.y*v.y + v.z*v.z + v.w*v.w;
        }
        s  += __shfl_xor_sync(0xffffffffu, s,  1);
        sq += __shfl_xor_sync(0xffffffffu, sq, 1);
        s  += __shfl_xor_sync(0xffffffffu, s,  2);
        sq += __shfl_xor_sync(0xffffffffu, sq, 2);
        const float mu  = s * (1.0f / DDIM);
        const float var = sq * (1.0f / DDIM) - mu * mu;
        const float rs  = rsqrtf(var + 1e-5f);
        #pragma unroll
        for (int j = 0; j < 8; ++j) {
            const int c = l4 * 4 + j * 16;
            const float4 v  = *(const float4*)&xr[c];
            const float4 gv = *(const float4*)&lng[c];
            const float4 bv = *(const float4*)&lnb[c];
            float4 o;
            o.x = tf32r((v.x - mu) * rs * gv.x + bv.x);
            o.y = tf32r((v.y - mu) * rs * gv.y + bv.y);
            o.z = tf32r((v.z - mu) * rs * gv.z + bv.z);
            o.w = tf32r((v.w - mu) * rs * gv.w + bv.w);
            *(float4*)&As[row][c] = o;
        }
    }
    __syncthreads();

    const int wid = tid >> 5, lane = tid & 31;
    const int g = lane >> 2, tig = lane & 3;
    const int wm = wid & 1, wn = wid >> 1;   // 2 x 4 warps
    const int m0 = wm * 32, n0 = wn * 32;

    if (gz) {
        // ================= FAST PATH: one dual pass: acc1=Wl, acc2=Wr ======
        float acc1[2][4][4] = {};
        float acc2[2][4][4] = {};
        const float* W1 = g_w + 0*16384;
        const float* W2 = g_w + 2*16384;

        int buf = 0;
        #pragma unroll 1
        for (int ch = 0; ch < 8; ++ch) {
            CP_WAIT0;
            __syncthreads();
            if (ch < 7) {
                const int kc = (ch + 1) * 16;
                #pragma unroll
                for (int u2 = 0; u2 < 2; ++u2) {
                    const int kk = lkk0 + u2 * 8;
                    const unsigned off = (unsigned)((((buf^1)*16*136) + kk*136 + lc4) << 2);
                    cpa16(bsAddr + off, W1 + (kc + kk) * 128 + lc4);
                    cpa16(gsAddr + off, W2 + (kc + kk) * 128 + lc4);
                }
                CP_COMMIT;
            }
            const int kc = ch * 16;
            #pragma unroll
            for (int ks = 0; ks < 16; ks += 8) {
                unsigned af[2][4], bf[4][2], gf[4][2];
                #pragma unroll
                for (int mt = 0; mt < 2; ++mt) {
                    const int m = m0 + mt * 16 + g;
                    af[mt][0] = __float_as_uint(As[m    ][kc + ks + tig]);
                    af[mt][1] = __float_as_uint(As[m + 8][kc + ks + tig]);
                    af[mt][2] = __float_as_uint(As[m    ][kc + ks + tig + 4]);
                    af[mt][3] = __float_as_uint(As[m + 8][kc + ks + tig + 4]);
                }
                #pragma unroll
                for (int nt = 0; nt < 4; ++nt) {
                    const int n = n0 + nt * 8 + g;
                    bf[nt][0] = __float_as_uint(Bs[buf][ks + tig    ][n]);
                    bf[nt][1] = __float_as_uint(Bs[buf][ks + tig + 4][n]);
                    gf[nt][0] = __float_as_uint(Gs[buf][ks + tig    ][n]);
                    gf[nt][1] = __float_as_uint(Gs[buf][ks + tig + 4][n]);
                }
                #pragma unroll
                for (int mt = 0; mt < 2; ++mt)
                    #pragma unroll
                    for (int nt = 0; nt < 4; ++nt) {
                        mma8(acc1[mt][nt], af[mt], bf[nt]);
                        mma8(acc2[mt][nt], af[mt], gf[nt]);
                    }
            }
            buf ^= 1;
        }

        // Let the einsum grid begin launching (it waits for our stores).
        pdl_trigger();

        // Merged epilogue: lt -> Ep, rt -> EpR (aliases As region, dead now).
        float (*EpR)[68] = (float(*)[68])dyn;
        __syncthreads();   // all As reads (last chunk mma) complete
        #pragma unroll
        for (int mt = 0; mt < 2; ++mt)
            #pragma unroll
            for (int nt = 0; nt < 4; ++nt)
                #pragma unroll
                for (int e = 0; e < 4; ++e) {
                    const int m = m0 + mt * 16 + g + ((e >> 1) << 3);
                    const int h = n0 + nt * 8 + 2 * tig + (e & 1);
                    float vl = (acc1[mt][nt][e] + bl[h]) * s_mk[m];
                    vl *= sigmoidf_(blg[h]);
                    Ep[h][m] = tf32r(vl);
                    float vr = (acc2[mt][nt][e] + br[h]) * s_mk[m];
                    vr *= sigmoidf_(brg[h]);
                    EpR[h][m] = tf32r(vr);
                }
        __syncthreads();
        #pragma unroll
        for (int it = 0; it < 32; ++it) {
            const int idx = it * 256 + tid;
            const int h = idx >> 6, m = idx & 63;
            const int q = s_q[m];
            if (q >= 0) {
                g_lt[(size_t)h * CP2 + q] = Ep[h][m];
                g_rt[(size_t)h * CP2 + q] = EpR[h][m];
            }
        }
        return;
    }

    // ================= FALLBACK: 3-pass path (256-thread shape) ============
    const float* b1s[3] = { bl, br, bog };
    const float* b2s[3] = { blg, brg, bog };

    #pragma unroll 1
    for (int pass = 0; pass < 3; ++pass) {
        const float* W1 = g_w + (size_t)(pass * 2) * 16384;   // 0,2,4
        const float* W2 = g_w + (size_t)(pass * 2 + 1) * 16384;
        const int dual = (pass < 2);

        float acc1[2][4][4] = {};
        float acc2[2][4][4] = {};

        int buf = 0;
        #pragma unroll 1
        for (int ch = 0; ch < 8; ++ch) {
            CP_WAIT0;
            __syncthreads();
            if (ch < 7) {
                const int kc = (ch + 1) * 16;
                #pragma unroll
                for (int u2 = 0; u2 < 2; ++u2) {
                    const int kk = lkk0 + u2 * 8;
                    const unsigned off = (unsigned)((((buf^1)*16*136) + kk*136 + lc4) << 2);
                    cpa16(bsAddr + off, W1 + (kc + kk) * 128 + lc4);
                    if (dual)
                        cpa16(gsAddr + off, W2 + (kc + kk) * 128 + lc4);
                }
                CP_COMMIT;
            }
            const int kc = ch * 16;
            #pragma unroll
            for (int ks = 0; ks < 16; ks += 8) {
                unsigned af[2][4], bf[4][2], gf[4][2];
                #pragma unroll
                for (int mt = 0; mt < 2; ++mt) {
                    const int m = m0 + mt * 16 + g;
                    af[mt][0] = __float_as_uint(As[m    ][kc + ks + tig]);
                    af[mt][1] = __float_as_uint(As[m + 8][kc + ks + tig]);
                    af[mt][2] = __float_as_uint(As[m    ][kc + ks + tig + 4]);
                    af[mt][3] = __float_as_uint(As[m + 8][kc + ks + tig + 4]);
                }
                #pragma unroll
                for (int nt = 0; nt < 4; ++nt) {
                    const int n = n0 + nt * 8 + g;
                    bf[nt][0] = __float_as_uint(Bs[buf][ks + tig    ][n]);
                    bf[nt][1] = __float_as_uint(Bs[buf][ks + tig + 4][n]);
                    if (dual) {
                        gf[nt][0] = __float_as_uint(Gs[buf][ks + tig    ][n]);
                        gf[nt][1] = __float_as_uint(Gs[buf][ks + tig + 4][n]);
                    }
                }
                #pragma unroll
                for (int mt = 0; mt < 2; ++mt)
                    #pragma unroll
                    for (int nt = 0; nt < 4; ++nt) {
                        mma8(acc1[mt][nt], af[mt], bf[nt]);
                        if (dual) mma8(acc2[mt][nt], af[mt], gf[nt]);
                    }
            }
            buf ^= 1;
        }

        // Hoisted prefetch of next pass chunk 0 into buf 0 (overlaps epilogue).
        if (pass == 0) {
            #pragma unroll
            for (int u2 = 0; u2 < 2; ++u2) {
                const int kk = lkk0 + u2 * 8;
                const unsigned off = (unsigned)((kk*136 + lc4) << 2);
                cpa16(bsAddr + off, g_w + 2*16384 + kk*128 + lc4);
                cpa16(gsAddr + off, g_w + 3*16384 + kk*128 + lc4);
            }
            CP_COMMIT;
        } else if (pass == 1) {
            #pragma unroll
            for (int u2 = 0; u2 < 2; ++u2) {
                const int kk = lkk0 + u2 * 8;
                const unsigned off = (unsigned)((kk*136 + lc4) << 2);
                cpa16(bsAddr + off, g_w + 4*16384 + kk*128 + lc4);
            }
            CP_COMMIT;
        }

        const float* b1 = b1s[pass];
        if (dual) {
            const float* b2 = b2s[pass];
            #pragma unroll
            for (int mt = 0; mt < 2; ++mt)
                #pragma unroll
                for (int nt = 0; nt < 4; ++nt)
                    #pragma unroll
                    for (int e = 0; e < 4; ++e) {
                        const int m = m0 + mt * 16 + g + ((e >> 1) << 3);
                        const int h = n0 + nt * 8 + 2 * tig + (e & 1);
                        float v = (acc1[mt][nt][e] + b1[h]) * s_mk[m];
                        v *= sigmoidf_(acc2[mt][nt][e] + b2[h]);
                        Ep[h][m] = tf32r(v);
                    }
            __syncthreads();
            float* outp = (pass == 0) ? g_lt : g_rt;
            #pragma unroll
            for (int it = 0; it < 32; ++it) {
                const int idx = it * 256 + tid;
                const int h = idx >> 6, m = idx & 63;
                const int q = s_q[m];
                if (q >= 0) outp[(size_t)h * CP2 + q] = Ep[h][m];
            }
            __syncthreads();
        } else {
            // out-gate: direct float2 stores, og[q][h]
            #pragma unroll
            for (int mt = 0; mt < 2; ++mt)
                #pragma unroll
                for (int nt = 0; nt < 4; ++nt) {
                    const int h = n0 + nt * 8 + 2 * tig;
                    const float bh0 = b1[h], bh1 = b1[h + 1];
                    {
                        const int m = m0 + mt * 16 + g;
                        const int q = s_q[m];
                        if (q >= 0) {
                            float2 v = { sigmoidf_(acc1[mt][nt][0] + bh0),
                                         sigmoidf_(acc1[mt][nt][1] + bh1) };
                            *(float2*)&g_og[(size_t)q * DDIM + h] = v;
                        }
                    }
                    {
                        const int m = m0 + mt * 16 + g + 8;
                        const int q = s_q[m];
                        if (q >= 0) {
                            float2 v = { sigmoidf_(acc1[mt][nt][2] + bh0),
                                         sigmoidf_(acc1[mt][nt][3] + bh1) };
                            *(float2*)&g_og[(size_t)q * DDIM + h] = v;
                        }
                    }
                }
        }
    }
    pdl_trigger();
}

// ---------------------------------------------------------------------------
// Kernel 2: einsum via tf32 mma, 4-stage cp.async ring (wait_group 2).
// Block 128x128, 256 threads (2x4 warps, 64x32 warp tile).
// PDL: fill branch (z>=128) is independent of proj -> runs immediately,
// overlapping proj's tail. Compute branch waits (griddepcontrol.wait)
// before touching g_lt/g_rt.
// ---------------------------------------------------------------------------
#define EIN_DYN_FLOATS (2*4*16*136)
__global__ __launch_bounds__(256) void einsum_kernel(
    const int* __restrict__ sm, const float* __restrict__ bo,
    float* __restrict__ out)
{
    const int tid = threadIdx.x;

    if (blockIdx.z >= 128) {
        // ---- fill branch: inactive rows -> bo. Independent of proj. ----
        pdl_trigger();
        if (g_fb) return;
        const int fb_id = (blockIdx.z - 128) * 16 + blockIdx.y * 4 + blockIdx.x;
        const int lane = tid & 31, wrp = tid >> 5;      // 8 warps, 1 row each
        const float4 b4 = *(const float4*)&bo[lane * 4];
        const int r0 = fb_id * 512;
        #pragma unroll 4
        for (int k = 0; k < 64; ++k) {
            const int r = r0 + k * 8 + wrp;
            const int i = r >> 9, j = r & (NSEQ - 1);
            if (sm[i] * sm[j]) continue;
            *(float4*)&out[(size_t)r * DDIM + lane * 4] = b4;
        }
        return;
    }

    const int cnt = g_cnt;
    const int i0 = blockIdx.y * 128;
    const int j0 = blockIdx.x * 128;
    if (i0 >= cnt || j0 >= cnt) return;
    const int CP = g_CP;
    const size_t CP2 = (size_t)g_CP2;
    const int d = blockIdx.z;
    const float* A = g_rt + (size_t)d * CP2;   // [k][i]
    const float* B = g_lt + (size_t)d * CP2;   // [k][j]

    extern __shared__ float edyn[];
    float (*As)[16][136] = (float(*)[16][136])edyn;                 // [4][16][136]
    float (*Bs)[16][136] = (float(*)[16][136])(edyn + 4*16*136);    // [4][16][136]

    const int wid = tid >> 5, lane = tid & 31;
    const int g = lane >> 2, tig = lane & 3;
    const int wm = wid & 1, wn = wid >> 1;   // 2 x 4
    const int m0 = wm * 64, n0 = wn * 32;

    const unsigned asAddr = smem_u32(&As[0][0][0]);
    const unsigned bsAddr = smem_u32(&Bs[0][0][0]);
    const int lkk0 = tid >> 5, lc4 = (tid & 31) * 4;

    float acc[4][4][4] = {};

    const int kend = (cnt + 15) & ~15;
    const int nch = kend >> 4;

    // Wait for proj's g_lt/g_rt stores to be visible, then start loading.
    pdl_wait();

    // prologue: prefetch chunks 0..2 into stages 0..2 (empty commits allowed)
    #pragma unroll
    for (int pc = 0; pc < 3; ++pc) {
        if (pc < nch) {
            #pragma unroll
            for (int u2 = 0; u2 < 2; ++u2) {
                const int kk = lkk0 + u2 * 8;
                const unsigned off = (unsigned)((pc*16*136 + kk*136 + lc4) << 2);
                cpa16(asAddr + off, A + (size_t)(pc*16 + kk) * CP + i0 + lc4);
                cpa16(bsAddr + off, B + (size_t)(pc*16 + kk) * CP + j0 + lc4);
            }
        }
        CP_COMMIT;
    }

    #pragma unroll 1
    for (int ch = 0; ch < nch; ++ch) {
        CP_WAIT2;
        __syncthreads();
        const int pf = ch + 3;
        if (pf < nch) {
            const int stg = pf & 3;
            #pragma unroll
            for (int u2 = 0; u2 < 2; ++u2) {
                const int kk = lkk0 + u2 * 8;
                const unsigned off = (unsigned)((stg*16*136 + kk*136 + lc4) << 2);
                cpa16(asAddr + off, A + (size_t)(pf*16 + kk) * CP + i0 + lc4);
                cpa16(bsAddr + off, B + (size_t)(pf*16 + kk) * CP + j0 + lc4);
            }
        }
        CP_COMMIT;
        const int cs = ch & 3;
        #pragma unroll
        for (int ks = 0; ks < 16; ks += 8) {
            unsigned af[4][4], bf[4][2];
            #pragma unroll
            for (int mt = 0; mt < 4; ++mt) {
                const int m = m0 + mt * 16 + g;
                af[mt][0] = __float_as_uint(As[cs][ks + tig    ][m]);
                af[mt][1] = __float_as_uint(As[cs][ks + tig    ][m + 8]);
                af[mt][2] = __float_as_uint(As[cs][ks + tig + 4][m]);
                af[mt][3] = __float_as_uint(As[cs][ks + tig + 4][m + 8]);
            }
            #pragma unroll
            for (int nt = 0; nt < 4; ++nt) {
                const int n = n0 + nt * 8 + g;
                bf[nt][0] = __float_as_uint(Bs[cs][ks + tig    ][n]);
                bf[nt][1] = __float_as_uint(Bs[cs][ks + tig + 4][n]);
            }
            #pragma unroll
            for (int mt = 0; mt < 4; ++mt)
                #pragma unroll
                for (int nt = 0; nt < 4; ++nt)
                    mma8(acc[mt][nt], af[mt], bf[nt]);
        }
    }

    // Let the final grid begin launching (it waits for our g_mm stores).
    pdl_trigger();

    #pragma unroll
    for (int mt = 0; mt < 4; ++mt)
        #pragma unroll
        for (int nt = 0; nt < 4; ++nt) {
            const int row = i0 + m0 + mt * 16 + g;
            const int col = j0 + n0 + nt * 8 + 2 * tig;
            float2 v0 = { acc[mt][nt][0], acc[mt][nt][1] };
            float2 v1 = { acc[mt][nt][2], acc[mt][nt][3] };
            *(float2*)&g_mm[(size_t)d * CP2 + (size_t)row * CP + col] = v0;
            *(float2*)&g_mm[(size_t)d * CP2 + (size_t)(row + 8) * CP + col] = v1;
        }
}

// ---------------------------------------------------------------------------
// Kernel 3: final: out = (_ln_h(mm) * og) @ Wo + bo. 64 pairs/block, 256 thr.
// PDL: sets up indices + Wo prefetch (independent), then waits before the
// g_mm gather. FAST PATH: og = sigmoid(bog[d]) inline.
// ---------------------------------------------------------------------------
#define FIN_DYN_FLOATS (128*68 + 64*132 + 2*16*136)
__global__ __launch_bounds__(256) void final_kernel(
    const float* __restrict__ olng, const float* __restrict__ olnb,
    const float* __restrict__ bog,
    const float* __restrict__ bo,   float* __restrict__ out)
{
    const int cnt2 = g_cnt2;
    const int p0 = blockIdx.x * 64;
    if (p0 >= cnt2) return;
    const int cnt = g_cnt, CP = g_CP;
    const size_t CP2 = (size_t)g_CP2;
    const int gz = (g_nzg == 0);

    extern __shared__ float dyn[];
    float (*s_mm)[68]    = (float(*)[68])dyn;                        // 128d x 68p
    float (*s_v)[132]    = (float(*)[132])(dyn + 128*68);            // 64p x 132d
    float (*Bs)[16][136] = (float(*)[16][136])(dyn + 128*68 + 64*132);

    __shared__ int s_q[64], s_ro[64];

    const int tid = threadIdx.x;
    if (tid < 64) {
        const int p = p0 + tid;
        if (p < cnt2) {
            const int ic = p / cnt, jc = p - ic * cnt;
            s_q[tid]  = ic * CP + jc;
            s_ro[tid] = (g_act[ic] << 9) + g_act[jc];
        } else { s_q[tid] = 0; s_ro[tid] = -1; }
    }

    const unsigned bsAddr = smem_u32(&Bs[0][0][0]);
    const float* Wo = g_w + 5 * 16384;
    const int lkk0 = tid >> 5, lc4 = (tid & 31) * 4;

    // prefetch Wo chunk 0 (independent of einsum): 16 rows via 2 rounds
    #pragma unroll
    for (int u2 = 0; u2 < 2; ++u2) {
        const int kk = lkk0 + u2 * 8;
        cpa16(bsAddr + (unsigned)((kk*136 + lc4) << 2), Wo + kk * 128 + lc4);
    }
    CP_COMMIT;
    __syncthreads();

    // Wait for einsum's g_mm stores to be visible.
    pdl_wait();

    #pragma unroll
    for (int it = 0; it < 32; ++it) {
        const int idx = it * 256 + tid;
        const int dd = idx >> 6, pp = idx & 63;
        s_mm[dd][pp] = g_mm[(size_t)dd * CP2 + s_q[pp]];
    }
    __syncthreads();

    {   // LN over d + gate: 4 threads per pair, 32 d's each
        const int p = tid >> 2, e = tid & 3;
        float s = 0.0f, sq = 0.0f;
        #pragma unroll
        for (int k = 0; k < 32; ++k) {
            const float v = s_mm[e * 32 + k][p];
            s += v; sq += v * v;
        }
        s  += __shfl_xor_sync(0xffffffffu, s,  1);
        sq += __shfl_xor_sync(0xffffffffu, sq, 1);
        s  += __shfl_xor_sync(0xffffffffu, s,  2);
        sq += __shfl_xor_sync(0xffffffffu, sq, 2);
        const float mu  = s * (1.0f / 128.0f);
        const float var = sq * (1.0f / 128.0f) - mu * mu;
        const float rs  = rsqrtf(var + 1e-5f);
        const float* ogr = g_og + (size_t)s_q[p] * DDIM + e * 32;
        #pragma unroll
        for (int j = 0; j < 8; ++j) {
            const int dbase = e * 32 + j * 4;
            float4 og4;
            if (gz) {
                const float4 bg = *(const float4*)&bog[dbase];
                og4.x = sigmoidf_(bg.x); og4.y = sigmoidf_(bg.y);
                og4.z = sigmoidf_(bg.z); og4.w = sigmoidf_(bg.w);
            } else {
                og4 = *(const float4*)&ogr[j * 4];
            }
            const float4 gg = *(const float4*)&olng[dbase];
            const float4 bb = *(const float4*)&olnb[dbase];
            float4 o;
            o.x = tf32r(((s_mm[dbase+0][p] - mu) * rs * gg.x + bb.x) * og4.x);
            o.y = tf32r(((s_mm[dbase+1][p] - mu) * rs * gg.y + bb.y) * og4.y);
            o.z = tf32r(((s_mm[dbase+2][p] - mu) * rs * gg.z + bb.z) * og4.z);
            o.w = tf32r(((s_mm[dbase+3][p] - mu) * rs * gg.w + bb.w) * og4.w);
            *(float4*)&s_v[p][dbase] = o;
        }
    }

    const int wid = tid >> 5, lane = tid & 31;
    const int g = lane >> 2, tig = lane & 3;
    const int wm = wid & 1, wn = wid >> 1;    // 2 x 4 warps, 32x32 tiles
    const int m0 = wm * 32, n0 = wn * 32;

    float acc[2][4][4] = {};

    int buf = 0;
    #pragma unroll 1
    for (int ch = 0; ch < 8; ++ch) {
        CP_WAIT0;
        __syncthreads();
        if (ch < 7) {
            const int kc = (ch + 1) * 16;
            #pragma unroll
            for (int u2 = 0; u2 < 2; ++u2) {
                const int kk = lkk0 + u2 * 8;
                const unsigned off = (unsigned)((((buf^1)*16*136) + kk*136 + lc4) << 2);
                cpa16(bsAddr + off, Wo + (kc + kk) * 128 + lc4);
            }
            CP_COMMIT;
        }
        const int kc = ch * 16;
        #pragma unroll
        for (int ks = 0; ks < 16; ks += 8) {
            unsigned af[2][4], bf[4][2];
            #pragma unroll
            for (int mt = 0; mt < 2; ++mt) {
                const int m = m0 + mt * 16 + g;
                af[mt][0] = __float_as_uint(s_v[m    ][kc + ks + tig]);
                af[mt][1] = __float_as_uint(s_v[m + 8][kc + ks + tig]);
                af[mt][2] = __float_as_uint(s_v[m    ][kc + ks + tig + 4]);
                af[mt][3] = __float_as_uint(s_v[m + 8][kc + ks + tig + 4]);
            }
            #pragma unroll
            for (int nt = 0; nt < 4; ++nt) {
                const int n = n0 + nt * 8 + g;
                bf[nt][0] = __float_as_uint(Bs[buf][ks + tig    ][n]);
                bf[nt][1] = __float_as_uint(Bs[buf][ks + tig + 4][n]);
            }
            #pragma unroll
            for (int mt = 0; mt < 2; ++mt)
                #pragma unroll
                for (int nt = 0; nt < 4; ++nt)
                    mma8(acc[mt][nt], af[mt], bf[nt]);
        }
        buf ^= 1;
    }

    #pragma unroll
    for (int mt = 0; mt < 2; ++mt)
        #pragma unroll
        for (int nt = 0; nt < 4; ++nt) {
            const int h = n0 + nt * 8 + 2 * tig;
            const float bh0 = bo[h], bh1 = bo[h + 1];
            {
                const int m = m0 + mt * 16 + g;
                const int ro = s_ro[m];
                if (ro >= 0) {
                    float2 v = { acc[mt][nt][0] + bh0, acc[mt][nt][1] + bh1 };
                    *(float2*)&out[(size_t)ro * DDIM + h] = v;
                }
            }
            {
                const int m = m0 + mt * 16 + g + 8;
                const int ro = s_ro[m];
                if (ro >= 0) {
                    float2 v = { acc[mt][nt][2] + bh0, acc[mt][nt][3] + bh1 };
                    *(float2*)&out[(size_t)ro * DDIM + h] = v;
                }
            }
        }
}

// ---------------------------------------------------------------------------
extern "C" void kernel_launch(void* const* d_in, const int* in_sizes, int n_in,
                              void* d_out, int out_size)
{
    const float* x    = (const float*)d_in[0];
    const int*   sm   = (const int*)  d_in[1];
    const float* lng  = (const float*)d_in[2];
    const float* lnb  = (const float*)d_in[3];
    const float* Wl   = (const float*)d_in[4];
    const float* bl   = (const float*)d_in[5];
    const float* Wr   = (const float*)d_in[6];
    const float* br   = (const float*)d_in[7];
    const float* Wlg  = (const float*)d_in[8];
    const float* blg  = (const float*)d_in[9];
    const float* Wrg  = (const float*)d_in[10];
    const float* brg  = (const float*)d_in[11];
    const float* Wog  = (const float*)d_in[12];
    const float* bog  = (const float*)d_in[13];
    const float* olng = (const float*)d_in[14];
    const float* olnb = (const float*)d_in[15];
    const float* Wo   = (const float*)d_in[16];
    const float* bo   = (const float*)d_in[17];
    float* out = (float*)d_out;

    const int projdyn = PROJ_DYN_FLOATS * 4;
    const int eindyn  = EIN_DYN_FLOATS * 4;
    const int findyn  = FIN_DYN_FLOATS * 4;
    cudaFuncSetAttribute(proj_kernel,
                         cudaFuncAttributeMaxDynamicSharedMemorySize, projdyn);
    cudaFuncSetAttribute(einsum_kernel,
                         cudaFuncAttributeMaxDynamicSharedMemorySize, eindyn);
    cudaFuncSetAttribute(final_kernel,
                         cudaFuncAttributeMaxDynamicSharedMemorySize, findyn);

    compact_kernel<<<1, 512>>>(sm, olnb);
    prep_w_kernel<<<384, 256>>>(Wl, Wlg, Wr, Wrg, Wog, Wo);

    proj_kernel<<<4096, 256, projdyn>>>(x, lng, lnb, sm, bl, blg, br, brg, bog);

    // einsum (PDL dependent on proj): z in [0,128) compute; [128,160) fill.
    {
        cudaLaunchAttribute at[1];
        at[0].id = cudaLaunchAttributeProgrammaticStreamSerialization;
        at[0].val.programmaticStreamSerializationAllowed = 1;
        cudaLaunchConfig_t cfg = {};
        cfg.gridDim = dim3(4, 4, 160);
        cfg.blockDim = dim3(256, 1, 1);
        cfg.dynamicSmemBytes = (size_t)eindyn;
        cfg.stream = 0;
        cfg.attrs = at;
        cfg.numAttrs = 1;
        cudaLaunchKernelEx(&cfg, einsum_kernel, sm, bo, out);
    }

    // final (PDL dependent on einsum).
    {
        cudaLaunchAttribute at[1];
        at[0].id = cudaLaunchAttributeProgrammaticStreamSerialization;
        at[0].val.programmaticStreamSerializationAllowed = 1;
        cudaLaunchConfig_t cfg = {};
        cfg.gridDim = dim3(4096, 1, 1);
        cfg.blockDim = dim3(256, 1, 1);
        cfg.dynamicSmemBytes = (size_t)findyn;
        cfg.stream = 0;
        cfg.attrs = at;
        cfg.numAttrs = 1;
        cudaLaunchKernelEx(&cfg, final_kernel, olng, olnb, bog, bo, out);
    }
}